// round 2
// baseline (speedup 1.0000x reference)
#include <cuda_runtime.h>
#include <cuda_bf16.h>
#include <math.h>

// ---------------- problem constants ----------------
#define BATCH 8
#define CCH 3
#define IMG 256
#define PP 8
#define HID 768
#define NLAYER 12
#define NHEAD 12
#define HD 64
#define TOK 1024          // (256/8)^2
#define MROWS (BATCH*TOK) // 8192
#define KPATCH (CCH*PP*PP) // 192
#define SS6 (6*HID)       // 4608
#define H4 (4*HID)        // 3072
#define H3 (3*HID)        // 2304
#define ATT_SCALE 0.036084391824351615f  // 1/sqrt(768)

// ---------------- scratch (device globals; no allocation APIs) ----------------
__device__ float g_xp[MROWS*KPATCH];
__device__ float g_cwT[KPATCH*HID];
__device__ float g_h[MROWS*HID];
__device__ float g_z[MROWS*HID];
__device__ float g_qkv[MROWS*H3];
__device__ float g_attno[MROWS*HID];
__device__ float g_mid[MROWS*H4];
__device__ float g_te0[BATCH*HID];
__device__ float g_tmid[BATCH*HID];
__device__ float g_te[BATCH*HID];
__device__ float g_ssmid[NLAYER*BATCH*SS6];
__device__ float g_ss[NLAYER*BATCH*SS6];
__device__ float g_y[MROWS*KPATCH];

// ---------------- helpers ----------------
__device__ __forceinline__ float posemb(int pos, int d) {
    int j = d >> 1;
    // freq = (1/10000)^(2j/768)
    float freq = expf(-9.210340371976184f * (float)(2 * j) * (1.0f / 768.0f));
    float th = (float)pos * freq;
    return (d & 1) ? cosf(th) : sinf(th);
}

// ================= main GEMM: C[M,N] = A[M,K] @ B[K,N] (+bias, epilogue) ==========
// Software-pipelined double-buffered SGEMM.
// EPI: 0 = bias only; 1 = gelu(acc+bias); 2 = C += alpha[b,n]*(acc+bias) (residual);
//      3 = acc + bias + posemb(tok, n)
// Requires: M % 128 == 0, K % 16 == 0 (all shapes here satisfy this).
#define BM 128
#define BN 128
#define BKK 16

template<int EPI>
__global__ void __launch_bounds__(256)
gemm_kernel(const float* __restrict__ A, const float* __restrict__ B,
            const float* __restrict__ bias, float* __restrict__ C,
            int M, int N, int K, const float* __restrict__ alpha)
{
    __shared__ float As[2][BKK][BM + 4];
    __shared__ float Bs[2][BKK][BN];
    int tid = threadIdx.x;
    int bm = blockIdx.y * BM, bn = blockIdx.x * BN;
    int tr = (tid >> 4) << 3;
    int tc = (tid & 15) << 3;
    float acc[8][8];
    #pragma unroll
    for (int i = 0; i < 8; i++)
        #pragma unroll
        for (int j = 0; j < 8; j++) acc[i][j] = 0.f;

    int aRow = tid >> 2;           // 0..63
    int aCol = (tid & 3) << 2;     // 0,4,8,12
    int bRow = tid >> 5;           // 0..7
    int bCol = (tid & 31) << 2;    // 0..124
    int bInRange = (bn + bCol) < N;

    const float* aPtr0 = A + (size_t)(bm + aRow) * K + aCol;
    const float* aPtr1 = A + (size_t)(bm + aRow + 64) * K + aCol;
    const float* bPtr0 = B + (size_t)bRow * N + bn + bCol;
    const float* bPtr1 = B + (size_t)(bRow + 8) * N + bn + bCol;

    float4 pa0, pa1, pb0, pb1;

    // ---- prologue: load tile 0 into regs, store into buffer 0 ----
    pa0 = *(const float4*)(aPtr0);
    pa1 = *(const float4*)(aPtr1);
    if (bInRange) { pb0 = *(const float4*)(bPtr0); pb1 = *(const float4*)(bPtr1); }
    else { pb0.x=pb0.y=pb0.z=pb0.w=0.f; pb1 = pb0; }

    As[0][aCol + 0][aRow] = pa0.x; As[0][aCol + 1][aRow] = pa0.y;
    As[0][aCol + 2][aRow] = pa0.z; As[0][aCol + 3][aRow] = pa0.w;
    As[0][aCol + 0][aRow + 64] = pa1.x; As[0][aCol + 1][aRow + 64] = pa1.y;
    As[0][aCol + 2][aRow + 64] = pa1.z; As[0][aCol + 3][aRow + 64] = pa1.w;
    *(float4*)&Bs[0][bRow][bCol]     = pb0;
    *(float4*)&Bs[0][bRow + 8][bCol] = pb1;
    __syncthreads();

    int nTiles = K / BKK;
    int cur = 0;
    for (int tI = 0; tI < nTiles; tI++) {
        // ---- prefetch tile tI+1 into registers (global loads issue early) ----
        int hasNext = (tI + 1) < nTiles;
        if (hasNext) {
            int koff = (tI + 1) * BKK;
            pa0 = *(const float4*)(aPtr0 + koff);
            pa1 = *(const float4*)(aPtr1 + koff);
            if (bInRange) {
                pb0 = *(const float4*)(bPtr0 + (size_t)koff * N);
                pb1 = *(const float4*)(bPtr1 + (size_t)koff * N);
            }
        }

        // ---- compute on buffer `cur` ----
        #pragma unroll
        for (int kk = 0; kk < BKK; kk++) {
            float a[8], b[8];
            *(float4*)(a)     = *(const float4*)&As[cur][kk][tr];
            *(float4*)(a + 4) = *(const float4*)&As[cur][kk][tr + 4];
            *(float4*)(b)     = *(const float4*)&Bs[cur][kk][tc];
            *(float4*)(b + 4) = *(const float4*)&Bs[cur][kk][tc + 4];
            #pragma unroll
            for (int i = 0; i < 8; i++)
                #pragma unroll
                for (int j = 0; j < 8; j++) acc[i][j] += a[i] * b[j];
        }

        // ---- store prefetched tile into the other buffer ----
        if (hasNext) {
            int nxt = cur ^ 1;
            As[nxt][aCol + 0][aRow] = pa0.x; As[nxt][aCol + 1][aRow] = pa0.y;
            As[nxt][aCol + 2][aRow] = pa0.z; As[nxt][aCol + 3][aRow] = pa0.w;
            As[nxt][aCol + 0][aRow + 64] = pa1.x; As[nxt][aCol + 1][aRow + 64] = pa1.y;
            As[nxt][aCol + 2][aRow + 64] = pa1.z; As[nxt][aCol + 3][aRow + 64] = pa1.w;
            *(float4*)&Bs[nxt][bRow][bCol]     = pb0;
            *(float4*)&Bs[nxt][bRow + 8][bCol] = pb1;
            __syncthreads();
            cur = nxt;
        }
    }

    #pragma unroll
    for (int i = 0; i < 8; i++) {
        int mrow = bm + tr + i;
        #pragma unroll
        for (int j = 0; j < 8; j++) {
            int ncol = bn + tc + j;
            if (ncol >= N) continue;
            float v = acc[i][j] + bias[ncol];
            size_t idx = (size_t)mrow * N + ncol;
            if (EPI == 1) {
                v = 0.5f * v * (1.0f + erff(v * 0.70710678118654752f));
                C[idx] = v;
            } else if (EPI == 2) {
                C[idx] = C[idx] + alpha[(mrow >> 10) * SS6 + ncol] * v;
            } else if (EPI == 3) {
                C[idx] = v + posemb(mrow & (TOK - 1), ncol);
            } else {
                C[idx] = v;
            }
        }
    }
}

// ============ small-M GEMM (M=8): out[8,N] = A[8,K] @ W[K,N] + b, opt silu ========
// grid: (N/128, nLayers), block 128.  K % 128 == 0, N % 128 == 0.
template<int SILU>
__global__ void __launch_bounds__(128)
smallgemm_kernel(const float* __restrict__ A, const float* __restrict__ W,
                 const float* __restrict__ bias, float* __restrict__ out,
                 int K, int N, long aStride, long wStride, long bStride, long oStride)
{
    int l = blockIdx.y;
    const float* Ap = A + (size_t)l * aStride;
    const float* Wp = W + (size_t)l * wStride;
    const float* bp = bias + (size_t)l * bStride;
    float* op = out + (size_t)l * oStride;
    int col = blockIdx.x * 128 + threadIdx.x;

    __shared__ float As[8][128];
    float acc[8];
    #pragma unroll
    for (int m = 0; m < 8; m++) acc[m] = 0.f;

    for (int k0 = 0; k0 < K; k0 += 128) {
        #pragma unroll
        for (int m = 0; m < 8; m++) As[m][threadIdx.x] = Ap[m * K + k0 + threadIdx.x];
        __syncthreads();
        #pragma unroll 4
        for (int kk = 0; kk < 128; kk++) {
            float w = Wp[(size_t)(k0 + kk) * N + col];
            #pragma unroll
            for (int m = 0; m < 8; m++) acc[m] += As[m][kk] * w;
        }
        __syncthreads();
    }
    #pragma unroll
    for (int m = 0; m < 8; m++) {
        float v = acc[m] + bp[col];
        if (SILU) v = v / (1.0f + expf(-v));
        op[(size_t)m * N + col] = v;
    }
}

// ================= LayerNorm + optional adaLN modulate =================
// z[row,:] = g1a * ( (x-mean)*rs*g + b ) + b1a     (ss==null -> plain LN)
__global__ void __launch_bounds__(256)
ln_mod_kernel(const float* __restrict__ x, float* __restrict__ z,
              const float* __restrict__ g, const float* __restrict__ bta,
              const float* __restrict__ ss, int gOff, int bOff)
{
    int row = blockIdx.x;
    int tid = threadIdx.x;
    const float* xr = x + (size_t)row * HID;
    float v[3], s = 0.f, s2 = 0.f;
    #pragma unroll
    for (int k = 0; k < 3; k++) {
        v[k] = xr[tid + k * 256];
        s += v[k]; s2 += v[k] * v[k];
    }
    #pragma unroll
    for (int o = 16; o; o >>= 1) {
        s  += __shfl_xor_sync(0xffffffffu, s, o);
        s2 += __shfl_xor_sync(0xffffffffu, s2, o);
    }
    __shared__ float ws[8], ws2[8];
    if ((tid & 31) == 0) { ws[tid >> 5] = s; ws2[tid >> 5] = s2; }
    __syncthreads();
    if (tid < 32) {
        float a  = (tid < 8) ? ws[tid]  : 0.f;
        float a2 = (tid < 8) ? ws2[tid] : 0.f;
        #pragma unroll
        for (int o = 4; o; o >>= 1) {
            a  += __shfl_xor_sync(0xffffffffu, a, o);
            a2 += __shfl_xor_sync(0xffffffffu, a2, o);
        }
        if (tid == 0) { ws[0] = a; ws2[0] = a2; }
    }
    __syncthreads();
    float mean = ws[0] * (1.0f / HID);
    float var  = ws2[0] * (1.0f / HID) - mean * mean;
    float rs = rsqrtf(var + 1e-5f);
    int bb = row >> 10;
    #pragma unroll
    for (int k = 0; k < 3; k++) {
        int c = tid + k * 256;
        float y = (v[k] - mean) * rs * g[c] + bta[c];
        if (ss) y = ss[bb * SS6 + gOff + c] * y + ss[bb * SS6 + bOff + c];
        z[(size_t)row * HID + c] = y;
    }
}

// ================= flash attention (fp32, HD=64, Qtile=64, KVtile=64) =============
// qkv layout: [b*1024+t, 2304] with q at col h*64, k at 768+h*64, v at 1536+h*64.
__global__ void __launch_bounds__(128)
flash_kernel(const float* __restrict__ qkv, float* __restrict__ o)
{
    __shared__ float Qs[64 * 64];   // [r][k]
    __shared__ float KsT[64 * 64];  // [k][c]; reused as P [r][s]
    __shared__ float Vs[64 * 64];   // [s][d]

    int bh = blockIdx.y;
    int b = bh / NHEAD, hh = bh % NHEAD;
    int qt0 = blockIdx.x * 64;
    int tid = threadIdx.x;
    const float* base = qkv + (size_t)b * TOK * H3 + hh * HD;

    // load Q tile
    {
        int r = tid >> 1, c0 = (tid & 1) * 32;
        const float* src = base + (size_t)(qt0 + r) * H3 + c0;
        float* dst = Qs + r * 64 + c0;
        #pragma unroll
        for (int i = 0; i < 8; i++)
            *(float4*)(dst + 4 * i) = *(const float4*)(src + 4 * i);
    }

    int ty = tid >> 4, tx = tid & 15;
    float mrow[8], lrow[8], acc[8][4];
    #pragma unroll
    for (int i = 0; i < 8; i++) {
        mrow[i] = -1e30f; lrow[i] = 0.f;
        acc[i][0] = acc[i][1] = acc[i][2] = acc[i][3] = 0.f;
    }

    for (int kt = 0; kt < TOK; kt += 64) {
        __syncthreads();   // prior-iter P / V consumers done; Q visible on iter 0
        {   // load K (transposed) and V tiles
            int r = tid >> 1, c0 = (tid & 1) * 32;
            const float* ksrc = base + 768  + (size_t)(kt + r) * H3 + c0;
            const float* vsrc = base + 1536 + (size_t)(kt + r) * H3 + c0;
            #pragma unroll
            for (int i = 0; i < 8; i++) {
                float4 kv = *(const float4*)(ksrc + 4 * i);
                int c = c0 + 4 * i;
                KsT[(c + 0) * 64 + r] = kv.x;
                KsT[(c + 1) * 64 + r] = kv.y;
                KsT[(c + 2) * 64 + r] = kv.z;
                KsT[(c + 3) * 64 + r] = kv.w;
                *(float4*)(Vs + r * 64 + c) = *(const float4*)(vsrc + 4 * i);
            }
        }
        __syncthreads();

        // S = Q @ K^T  (thread: rows ty*8+i, cols tx*4+j)
        float s[8][4];
        #pragma unroll
        for (int i = 0; i < 8; i++) { s[i][0]=0;s[i][1]=0;s[i][2]=0;s[i][3]=0; }
        for (int k0 = 0; k0 < 64; k0 += 4) {
            float4 q4[8];
            #pragma unroll
            for (int i = 0; i < 8; i++)
                q4[i] = *(const float4*)&Qs[(ty * 8 + i) * 64 + k0];
            #pragma unroll
            for (int kq = 0; kq < 4; kq++) {
                float4 kv = *(const float4*)&KsT[(k0 + kq) * 64 + tx * 4];
                #pragma unroll
                for (int i = 0; i < 8; i++) {
                    float qv = (kq == 0) ? q4[i].x : (kq == 1) ? q4[i].y :
                               (kq == 2) ? q4[i].z : q4[i].w;
                    s[i][0] += qv * kv.x; s[i][1] += qv * kv.y;
                    s[i][2] += qv * kv.z; s[i][3] += qv * kv.w;
                }
            }
        }

        // online softmax update
        float p[8][4];
        #pragma unroll
        for (int i = 0; i < 8; i++) {
            float sc0 = s[i][0]*ATT_SCALE, sc1 = s[i][1]*ATT_SCALE;
            float sc2 = s[i][2]*ATT_SCALE, sc3 = s[i][3]*ATT_SCALE;
            float mloc = fmaxf(fmaxf(sc0, sc1), fmaxf(sc2, sc3));
            #pragma unroll
            for (int off = 8; off; off >>= 1)
                mloc = fmaxf(mloc, __shfl_xor_sync(0xffffffffu, mloc, off, 16));
            float mnew = fmaxf(mrow[i], mloc);
            float corr = expf(mrow[i] - mnew);
            p[i][0] = expf(sc0 - mnew); p[i][1] = expf(sc1 - mnew);
            p[i][2] = expf(sc2 - mnew); p[i][3] = expf(sc3 - mnew);
            float ps = p[i][0] + p[i][1] + p[i][2] + p[i][3];
            #pragma unroll
            for (int off = 8; off; off >>= 1)
                ps += __shfl_xor_sync(0xffffffffu, ps, off, 16);
            lrow[i] = lrow[i] * corr + ps;
            mrow[i] = mnew;
            acc[i][0] *= corr; acc[i][1] *= corr;
            acc[i][2] *= corr; acc[i][3] *= corr;
        }

        __syncthreads();               // everyone done reading KsT
        #pragma unroll
        for (int i = 0; i < 8; i++) {  // P into KsT buffer as [r][s]
            float4 pv = make_float4(p[i][0], p[i][1], p[i][2], p[i][3]);
            *(float4*)&KsT[(ty * 8 + i) * 64 + tx * 4] = pv;
        }
        __syncthreads();

        // O += P @ V
        for (int s0 = 0; s0 < 64; s0 += 4) {
            float4 p4[8];
            #pragma unroll
            for (int i = 0; i < 8; i++)
                p4[i] = *(const float4*)&KsT[(ty * 8 + i) * 64 + s0];
            #pragma unroll
            for (int sq = 0; sq < 4; sq++) {
                float4 vv = *(const float4*)&Vs[(s0 + sq) * 64 + tx * 4];
                #pragma unroll
                for (int i = 0; i < 8; i++) {
                    float pvv = (sq == 0) ? p4[i].x : (sq == 1) ? p4[i].y :
                                (sq == 2) ? p4[i].z : p4[i].w;
                    acc[i][0] += pvv * vv.x; acc[i][1] += pvv * vv.y;
                    acc[i][2] += pvv * vv.z; acc[i][3] += pvv * vv.w;
                }
            }
        }
    }

    #pragma unroll
    for (int i = 0; i < 8; i++) {
        float inv = 1.0f / lrow[i];
        int r = ty * 8 + i, d = tx * 4;
        float* dst = o + (size_t)(b * TOK + qt0 + r) * HID + hh * HD + d;
        dst[0] = acc[i][0] * inv; dst[1] = acc[i][1] * inv;
        dst[2] = acc[i][2] * inv; dst[3] = acc[i][3] * inv;
    }
}

// ================= misc small kernels =================
__global__ void tconv_kernel(const float* __restrict__ w, float* __restrict__ wT) {
    int idx = blockIdx.x * 256 + threadIdx.x;
    if (idx >= HID * KPATCH) return;
    int d = idx / KPATCH, k = idx % KPATCH;
    wT[k * HID + d] = w[idx];
}

__global__ void patch_kernel(const float* __restrict__ x, float* __restrict__ xp) {
    int idx = blockIdx.x * 256 + threadIdx.x;
    if (idx >= MROWS * KPATCH) return;
    int m = idx / KPATCH, k = idx % KPATCH;
    int b = m >> 10, tok = m & 1023, gy = tok >> 5, gx = tok & 31;
    int c = k >> 6, r = k & 63, p = r >> 3, q = r & 7;
    xp[idx] = x[((size_t)(b * CCH + c) * IMG + (gy * 8 + p)) * IMG + gx * 8 + q];
}

__global__ void te0_kernel(const int* __restrict__ t, float* __restrict__ te0) {
    int idx = blockIdx.x * 256 + threadIdx.x;
    if (idx >= BATCH * HID) return;
    int b = idx / HID, d = idx % HID;
    te0[idx] = posemb(t[b], d);
}

__global__ void unpatch_kernel(const float* __restrict__ y, float* __restrict__ out) {
    int idx = blockIdx.x * 256 + threadIdx.x;
    if (idx >= BATCH * CCH * IMG * IMG) return;
    int b = idx / (CCH * IMG * IMG);
    int rem = idx % (CCH * IMG * IMG);
    int c = rem / (IMG * IMG);
    int pix = rem % (IMG * IMG);
    int yy = pix >> 8, xx = pix & 255;
    int gy = yy >> 3, p = yy & 7, gx = xx >> 3, q = xx & 7;
    out[idx] = y[(size_t)(b * TOK + gy * 32 + gx) * KPATCH + p * 24 + q * 3 + c];
}

// ================= host launcher =================
static float* symAddr(const void* sym) {
    void* p = nullptr;
    cudaGetSymbolAddress(&p, sym);
    return (float*)p;
}

extern "C" void kernel_launch(void* const* d_in, const int* in_sizes, int n_in,
                              void* d_out, int out_size)
{
    const float* x       = (const float*)d_in[0];
    const int*   t       = (const int*)  d_in[1];
    const float* conv_w  = (const float*)d_in[2];
    const float* conv_b  = (const float*)d_in[3];
    const float* te_w1   = (const float*)d_in[4];
    const float* te_b1   = (const float*)d_in[5];
    const float* te_w2   = (const float*)d_in[6];
    const float* te_b2   = (const float*)d_in[7];
    const float* ln1_g   = (const float*)d_in[8];
    const float* ln1_b   = (const float*)d_in[9];
    const float* ln2_g   = (const float*)d_in[10];
    const float* ln2_b   = (const float*)d_in[11];
    const float* qkv_w   = (const float*)d_in[12];
    const float* qkv_b   = (const float*)d_in[13];
    const float* mha_w1  = (const float*)d_in[14];
    const float* mha_b1  = (const float*)d_in[15];
    const float* mha_w2  = (const float*)d_in[16];
    const float* mha_b2  = (const float*)d_in[17];
    const float* ss_w1   = (const float*)d_in[18];
    const float* ss_b1   = (const float*)d_in[19];
    const float* ss_w2   = (const float*)d_in[20];
    const float* ss_b2   = (const float*)d_in[21];
    const float* ffn_w1  = (const float*)d_in[22];
    const float* ffn_b1  = (const float*)d_in[23];
    const float* ffn_w2  = (const float*)d_in[24];
    const float* ffn_b2  = (const float*)d_in[25];
    const float* lnf_g   = (const float*)d_in[26];
    const float* lnf_b   = (const float*)d_in[27];
    const float* out_w   = (const float*)d_in[28];
    const float* out_b   = (const float*)d_in[29];
    float* out = (float*)d_out;

    float* xp    = symAddr(g_xp);
    float* cwT   = symAddr(g_cwT);
    float* h     = symAddr(g_h);
    float* z     = symAddr(g_z);
    float* qkv   = symAddr(g_qkv);
    float* attno = symAddr(g_attno);
    float* mid   = symAddr(g_mid);
    float* te0   = symAddr(g_te0);
    float* tmid  = symAddr(g_tmid);
    float* te    = symAddr(g_te);
    float* ssmid = symAddr(g_ssmid);
    float* ssb   = symAddr(g_ss);
    float* yb    = symAddr(g_y);

    // --- patchify + pos emb ---
    tconv_kernel<<<(HID * KPATCH + 255) / 256, 256>>>(conv_w, cwT);
    patch_kernel<<<(MROWS * KPATCH + 255) / 256, 256>>>(x, xp);
    gemm_kernel<3><<<dim3(HID / BN, MROWS / BM), 256>>>(xp, cwT, conv_b, h,
                                                        MROWS, HID, KPATCH, nullptr);

    // --- timestep embedding MLP ---
    te0_kernel<<<(BATCH * HID + 255) / 256, 256>>>(t, te0);
    smallgemm_kernel<1><<<dim3(HID / 128, 1), 128>>>(te0, te_w1, te_b1, tmid,
                                                     HID, HID, 0, 0, 0, 0);
    smallgemm_kernel<0><<<dim3(HID / 128, 1), 128>>>(tmid, te_w2, te_b2, te,
                                                     HID, HID, 0, 0, 0, 0);

    // --- all 12 layers' adaLN modulation vectors up front ---
    smallgemm_kernel<1><<<dim3(SS6 / 128, NLAYER), 128>>>(
        te, ss_w1, ss_b1, ssmid, HID, SS6,
        0, (long)HID * SS6, SS6, (long)BATCH * SS6);
    smallgemm_kernel<0><<<dim3(SS6 / 128, NLAYER), 128>>>(
        ssmid, ss_w2, ss_b2, ssb, SS6, SS6,
        (long)BATCH * SS6, (long)SS6 * SS6, SS6, (long)BATCH * SS6);

    // --- transformer layers ---
    for (int l = 0; l < NLAYER; l++) {
        const float* ssl = ssb + (size_t)l * BATCH * SS6;

        ln_mod_kernel<<<MROWS, 256>>>(h, z, ln1_g + l * HID, ln1_b + l * HID,
                                      ssl, 0, HID);
        gemm_kernel<0><<<dim3(H3 / BN, MROWS / BM), 256>>>(
            z, qkv_w + (size_t)l * HID * H3, qkv_b + l * H3, qkv,
            MROWS, H3, HID, nullptr);
        flash_kernel<<<dim3(TOK / 64, BATCH * NHEAD), 128>>>(qkv, attno);
        gemm_kernel<1><<<dim3(H4 / BN, MROWS / BM), 256>>>(
            attno, mha_w1 + (size_t)l * HID * H4, mha_b1 + l * H4, mid,
            MROWS, H4, HID, nullptr);
        gemm_kernel<2><<<dim3(HID / BN, MROWS / BM), 256>>>(
            mid, mha_w2 + (size_t)l * H4 * HID, mha_b2 + l * HID, h,
            MROWS, HID, H4, ssl + 2 * HID);

        ln_mod_kernel<<<MROWS, 256>>>(h, z, ln2_g + l * HID, ln2_b + l * HID,
                                      ssl, 3 * HID, 4 * HID);
        gemm_kernel<1><<<dim3(H4 / BN, MROWS / BM), 256>>>(
            z, ffn_w1 + (size_t)l * HID * H4, ffn_b1 + l * H4, mid,
            MROWS, H4, HID, nullptr);
        gemm_kernel<2><<<dim3(HID / BN, MROWS / BM), 256>>>(
            mid, ffn_w2 + (size_t)l * H4 * HID, ffn_b2 + l * HID, h,
            MROWS, HID, H4, ssl + 5 * HID);
    }

    // --- final LN, projection, unpatchify ---
    ln_mod_kernel<<<MROWS, 256>>>(h, z, lnf_g, lnf_b, nullptr, 0, 0);
    gemm_kernel<0><<<dim3((KPATCH + BN - 1) / BN, MROWS / BM), 256>>>(
        z, out_w, out_b, yb, MROWS, KPATCH, HID, nullptr);
    unpatch_kernel<<<(BATCH * CCH * IMG * IMG + 255) / 256, 256>>>(yb, out);
}

// round 6
// speedup vs baseline: 2.0543x; 2.0543x over previous
#include <cuda_runtime.h>
#include <cuda_bf16.h>
#include <math.h>
#include <stdint.h>

// ---------------- problem constants ----------------
#define BATCH 8
#define CCH 3
#define IMG 256
#define PP 8
#define HID 768
#define NLAYER 12
#define NHEAD 12
#define HD 64
#define TOK 1024          // (256/8)^2
#define MROWS (BATCH*TOK) // 8192
#define KPATCH (CCH*PP*PP) // 192
#define SS6 (6*HID)       // 4608
#define H4 (4*HID)        // 3072
#define H3 (3*HID)        // 2304
#define ATT_SCALE 0.036084391824351615f  // 1/sqrt(768)

// ---------------- scratch (device globals; no allocation APIs) ----------------
__device__ float g_xp[MROWS*KPATCH];
__device__ float g_cwT[KPATCH*HID];
__device__ float g_h[MROWS*HID];
__device__ float g_z[MROWS*HID];
__device__ float g_qkv[MROWS*H3];
__device__ float g_attno[MROWS*HID];
__device__ float g_mid[MROWS*H4];
__device__ float g_te0[BATCH*HID];
__device__ float g_tmid[BATCH*HID];
__device__ float g_te[BATCH*HID];
__device__ float g_ssmid[NLAYER*BATCH*SS6];
__device__ float g_ss[NLAYER*BATCH*SS6];
__device__ float g_y[MROWS*KPATCH];

// ---------------- helpers ----------------
__device__ __forceinline__ float posemb(int pos, int d) {
    int j = d >> 1;
    float freq = expf(-9.210340371976184f * (float)(2 * j) * (1.0f / 768.0f));
    float th = (float)pos * freq;
    return (d & 1) ? cosf(th) : sinf(th);
}

__device__ __forceinline__ float to_tf32(float x) {
    float r;
    asm("cvt.rna.tf32.f32 %0, %1;" : "=f"(r) : "f"(x));
    return r;
}

__device__ __forceinline__ void mma_tf32(float c[4],
    uint32_t a0, uint32_t a1, uint32_t a2, uint32_t a3,
    uint32_t b0, uint32_t b1)
{
    asm volatile(
        "mma.sync.aligned.m16n8k8.row.col.f32.tf32.tf32.f32 "
        "{%0,%1,%2,%3}, {%4,%5,%6,%7}, {%8,%9}, {%0,%1,%2,%3};\n"
        : "+f"(c[0]), "+f"(c[1]), "+f"(c[2]), "+f"(c[3])
        : "r"(a0), "r"(a1), "r"(a2), "r"(a3), "r"(b0), "r"(b1));
}

// ================= main GEMM (tf32 tensor cores) ==========================
// C[M,N] = A[M,K] @ B[K,N] (+bias, epilogue), fp32 in/out, tf32 mma inside.
// EPI: 0 = bias; 1 = gelu(acc+bias); 2 = C += alpha[b,n]*(acc+bias);
//      3 = acc + bias + posemb(tok, n)
// Requires: M % 128 == 0, K % 16 == 0, N % 4 == 0.
#define BM 128
#define BN 128
#define BK 16
#define SPAD 8
#define SLD (BM + SPAD)   // 136: (k-row stride) % 32 == 8 -> conflict-free frags

template<int EPI>
__global__ void __launch_bounds__(256)
gemm_tc(const float* __restrict__ A, const float* __restrict__ B,
        const float* __restrict__ bias, float* __restrict__ C,
        int M, int N, int K, const float* __restrict__ alpha)
{
    __shared__ float As[2][BK][SLD];   // [k][m]
    __shared__ float Bs[2][BK][SLD];   // [k][n]

    int tid = threadIdx.x;
    int wid = tid >> 5, lane = tid & 31;
    int groupID = lane >> 2, tig = lane & 3;
    int warpM = (wid & 1) * 64;
    int warpN = (wid >> 1) * 32;
    int bm = blockIdx.y * BM, bn = blockIdx.x * BN;

    float acc[4][4][4];
    #pragma unroll
    for (int i = 0; i < 4; i++)
        #pragma unroll
        for (int j = 0; j < 4; j++)
            #pragma unroll
            for (int r = 0; r < 4; r++) acc[i][j][r] = 0.f;

    // global-load mapping
    int aRow = tid >> 1;               // 0..127
    int aC = (tid & 1) * 8;            // 0 or 8; two float4 at aC, aC+4
    int bRow = tid >> 4;               // 0..15
    int bC = (tid & 15) * 8;           // 0..120; two float4 at bC, bC+4

    const float* aPtr = A + (size_t)(bm + aRow) * K + aC;
    const float* bPtr = B + (size_t)bRow * N + bn + bC;
    int bOk0 = (bn + bC) < N;
    int bOk1 = (bn + bC + 4) < N;

    float4 pa0, pa1, pb0, pb1;
    const float4 z4 = make_float4(0.f, 0.f, 0.f, 0.f);

    // ---- prologue: tile 0 ----
    pa0 = *(const float4*)(aPtr);
    pa1 = *(const float4*)(aPtr + 4);
    pb0 = bOk0 ? *(const float4*)(bPtr) : z4;
    pb1 = bOk1 ? *(const float4*)(bPtr + 4) : z4;

    {
        As[0][aC + 0][aRow] = to_tf32(pa0.x); As[0][aC + 1][aRow] = to_tf32(pa0.y);
        As[0][aC + 2][aRow] = to_tf32(pa0.z); As[0][aC + 3][aRow] = to_tf32(pa0.w);
        As[0][aC + 4][aRow] = to_tf32(pa1.x); As[0][aC + 5][aRow] = to_tf32(pa1.y);
        As[0][aC + 6][aRow] = to_tf32(pa1.z); As[0][aC + 7][aRow] = to_tf32(pa1.w);
        float4 q0 = make_float4(to_tf32(pb0.x), to_tf32(pb0.y), to_tf32(pb0.z), to_tf32(pb0.w));
        float4 q1 = make_float4(to_tf32(pb1.x), to_tf32(pb1.y), to_tf32(pb1.z), to_tf32(pb1.w));
        *(float4*)&Bs[0][bRow][bC]     = q0;
        *(float4*)&Bs[0][bRow][bC + 4] = q1;
    }
    __syncthreads();

    int nTiles = K / BK;
    int cur = 0;
    for (int tI = 0; tI < nTiles; tI++) {
        int hasNext = (tI + 1) < nTiles;
        if (hasNext) {
            int koff = (tI + 1) * BK;
            pa0 = *(const float4*)(aPtr + koff);
            pa1 = *(const float4*)(aPtr + koff + 4);
            pb0 = bOk0 ? *(const float4*)(bPtr + (size_t)koff * N) : z4;
            pb1 = bOk1 ? *(const float4*)(bPtr + (size_t)koff * N + 4) : z4;
        }

        // ---- compute on buffer `cur`: two k8 sub-steps ----
        #pragma unroll
        for (int ks = 0; ks < 2; ks++) {
            int kb = ks * 8;
            uint32_t af[4][4];
            #pragma unroll
            for (int mi = 0; mi < 4; mi++) {
                int mr = warpM + mi * 16 + groupID;
                af[mi][0] = __float_as_uint(As[cur][kb + tig][mr]);
                af[mi][1] = __float_as_uint(As[cur][kb + tig][mr + 8]);
                af[mi][2] = __float_as_uint(As[cur][kb + tig + 4][mr]);
                af[mi][3] = __float_as_uint(As[cur][kb + tig + 4][mr + 8]);
            }
            uint32_t bf[4][2];
            #pragma unroll
            for (int ni = 0; ni < 4; ni++) {
                int nc = warpN + ni * 8 + groupID;
                bf[ni][0] = __float_as_uint(Bs[cur][kb + tig][nc]);
                bf[ni][1] = __float_as_uint(Bs[cur][kb + tig + 4][nc]);
            }
            #pragma unroll
            for (int mi = 0; mi < 4; mi++)
                #pragma unroll
                for (int ni = 0; ni < 4; ni++)
                    mma_tf32(acc[mi][ni], af[mi][0], af[mi][1], af[mi][2], af[mi][3],
                             bf[ni][0], bf[ni][1]);
        }

        if (hasNext) {
            int nxt = cur ^ 1;
            As[nxt][aC + 0][aRow] = to_tf32(pa0.x); As[nxt][aC + 1][aRow] = to_tf32(pa0.y);
            As[nxt][aC + 2][aRow] = to_tf32(pa0.z); As[nxt][aC + 3][aRow] = to_tf32(pa0.w);
            As[nxt][aC + 4][aRow] = to_tf32(pa1.x); As[nxt][aC + 5][aRow] = to_tf32(pa1.y);
            As[nxt][aC + 6][aRow] = to_tf32(pa1.z); As[nxt][aC + 7][aRow] = to_tf32(pa1.w);
            float4 q0 = make_float4(to_tf32(pb0.x), to_tf32(pb0.y), to_tf32(pb0.z), to_tf32(pb0.w));
            float4 q1 = make_float4(to_tf32(pb1.x), to_tf32(pb1.y), to_tf32(pb1.z), to_tf32(pb1.w));
            *(float4*)&Bs[nxt][bRow][bC]     = q0;
            *(float4*)&Bs[nxt][bRow][bC + 4] = q1;
            __syncthreads();
            cur = nxt;
        }
    }

    // ---- epilogue ----
    #pragma unroll
    for (int mi = 0; mi < 4; mi++) {
        #pragma unroll
        for (int ni = 0; ni < 4; ni++) {
            int row0 = bm + warpM + mi * 16 + groupID;
            int col = bn + warpN + ni * 8 + tig * 2;
            if (col >= N) continue;
            #pragma unroll
            for (int half = 0; half < 2; half++) {
                int mrow = row0 + half * 8;
                float v0 = acc[mi][ni][half * 2 + 0] + bias[col];
                float v1 = acc[mi][ni][half * 2 + 1] + bias[col + 1];
                size_t idx = (size_t)mrow * N + col;
                if (EPI == 1) {
                    v0 = 0.5f * v0 * (1.0f + erff(v0 * 0.70710678118654752f));
                    v1 = 0.5f * v1 * (1.0f + erff(v1 * 0.70710678118654752f));
                    C[idx] = v0; C[idx + 1] = v1;
                } else if (EPI == 2) {
                    int bb = mrow >> 10;
                    C[idx]     = C[idx]     + alpha[bb * SS6 + col]     * v0;
                    C[idx + 1] = C[idx + 1] + alpha[bb * SS6 + col + 1] * v1;
                } else if (EPI == 3) {
                    int tok = mrow & (TOK - 1);
                    C[idx]     = v0 + posemb(tok, col);
                    C[idx + 1] = v1 + posemb(tok, col + 1);
                } else {
                    C[idx] = v0; C[idx + 1] = v1;
                }
            }
        }
    }
}

// ============ small-M GEMM (M=8): out[8,N] = A[8,K] @ W[K,N] + b, opt silu ========
template<int SILU>
__global__ void __launch_bounds__(128)
smallgemm_kernel(const float* __restrict__ A, const float* __restrict__ W,
                 const float* __restrict__ bias, float* __restrict__ out,
                 int K, int N, long aStride, long wStride, long bStride, long oStride)
{
    int l = blockIdx.y;
    const float* Ap = A + (size_t)l * aStride;
    const float* Wp = W + (size_t)l * wStride;
    const float* bp = bias + (size_t)l * bStride;
    float* op = out + (size_t)l * oStride;
    int col = blockIdx.x * 128 + threadIdx.x;

    __shared__ float As[8][128];
    float acc[8];
    #pragma unroll
    for (int m = 0; m < 8; m++) acc[m] = 0.f;

    for (int k0 = 0; k0 < K; k0 += 128) {
        #pragma unroll
        for (int m = 0; m < 8; m++) As[m][threadIdx.x] = Ap[m * K + k0 + threadIdx.x];
        __syncthreads();
        #pragma unroll 4
        for (int kk = 0; kk < 128; kk++) {
            float w = Wp[(size_t)(k0 + kk) * N + col];
            #pragma unroll
            for (int m = 0; m < 8; m++) acc[m] += As[m][kk] * w;
        }
        __syncthreads();
    }
    #pragma unroll
    for (int m = 0; m < 8; m++) {
        float v = acc[m] + bp[col];
        if (SILU) v = v / (1.0f + expf(-v));
        op[(size_t)m * N + col] = v;
    }
}

// ================= LayerNorm + optional adaLN modulate =================
__global__ void __launch_bounds__(256)
ln_mod_kernel(const float* __restrict__ x, float* __restrict__ z,
              const float* __restrict__ g, const float* __restrict__ bta,
              const float* __restrict__ ss, int gOff, int bOff)
{
    int row = blockIdx.x;
    int tid = threadIdx.x;
    const float* xr = x + (size_t)row * HID;
    float v[3], s = 0.f, s2 = 0.f;
    #pragma unroll
    for (int k = 0; k < 3; k++) {
        v[k] = xr[tid + k * 256];
        s += v[k]; s2 += v[k] * v[k];
    }
    #pragma unroll
    for (int o = 16; o; o >>= 1) {
        s  += __shfl_xor_sync(0xffffffffu, s, o);
        s2 += __shfl_xor_sync(0xffffffffu, s2, o);
    }
    __shared__ float ws[8], ws2[8];
    if ((tid & 31) == 0) { ws[tid >> 5] = s; ws2[tid >> 5] = s2; }
    __syncthreads();
    if (tid < 32) {
        float a  = (tid < 8) ? ws[tid]  : 0.f;
        float a2 = (tid < 8) ? ws2[tid] : 0.f;
        #pragma unroll
        for (int o = 4; o; o >>= 1) {
            a  += __shfl_xor_sync(0xffffffffu, a, o);
            a2 += __shfl_xor_sync(0xffffffffu, a2, o);
        }
        if (tid == 0) { ws[0] = a; ws2[0] = a2; }
    }
    __syncthreads();
    float mean = ws[0] * (1.0f / HID);
    float var  = ws2[0] * (1.0f / HID) - mean * mean;
    float rs = rsqrtf(var + 1e-5f);
    int bb = row >> 10;
    #pragma unroll
    for (int k = 0; k < 3; k++) {
        int c = tid + k * 256;
        float y = (v[k] - mean) * rs * g[c] + bta[c];
        if (ss) y = ss[bb * SS6 + gOff + c] * y + ss[bb * SS6 + bOff + c];
        z[(size_t)row * HID + c] = y;
    }
}

// ================= flash attention (fp32, HD=64, Qtile=64, KVtile=64) =============
__global__ void __launch_bounds__(128)
flash_kernel(const float* __restrict__ qkv, float* __restrict__ o)
{
    __shared__ float Qs[64 * 64];
    __shared__ float KsT[64 * 64];
    __shared__ float Vs[64 * 64];

    int bh = blockIdx.y;
    int b = bh / NHEAD, hh = bh % NHEAD;
    int qt0 = blockIdx.x * 64;
    int tid = threadIdx.x;
    const float* base = qkv + (size_t)b * TOK * H3 + hh * HD;

    {
        int r = tid >> 1, c0 = (tid & 1) * 32;
        const float* src = base + (size_t)(qt0 + r) * H3 + c0;
        float* dst = Qs + r * 64 + c0;
        #pragma unroll
        for (int i = 0; i < 8; i++)
            *(float4*)(dst + 4 * i) = *(const float4*)(src + 4 * i);
    }

    int ty = tid >> 4, tx = tid & 15;
    float mrow[8], lrow[8], acc[8][4];
    #pragma unroll
    for (int i = 0; i < 8; i++) {
        mrow[i] = -1e30f; lrow[i] = 0.f;
        acc[i][0] = acc[i][1] = acc[i][2] = acc[i][3] = 0.f;
    }

    for (int kt = 0; kt < TOK; kt += 64) {
        __syncthreads();
        {
            int r = tid >> 1, c0 = (tid & 1) * 32;
            const float* ksrc = base + 768  + (size_t)(kt + r) * H3 + c0;
            const float* vsrc = base + 1536 + (size_t)(kt + r) * H3 + c0;
            #pragma unroll
            for (int i = 0; i < 8; i++) {
                float4 kv = *(const float4*)(ksrc + 4 * i);
                int c = c0 + 4 * i;
                KsT[(c + 0) * 64 + r] = kv.x;
                KsT[(c + 1) * 64 + r] = kv.y;
                KsT[(c + 2) * 64 + r] = kv.z;
                KsT[(c + 3) * 64 + r] = kv.w;
                *(float4*)(Vs + r * 64 + c) = *(const float4*)(vsrc + 4 * i);
            }
        }
        __syncthreads();

        float s[8][4];
        #pragma unroll
        for (int i = 0; i < 8; i++) { s[i][0]=0;s[i][1]=0;s[i][2]=0;s[i][3]=0; }
        for (int k0 = 0; k0 < 64; k0 += 4) {
            float4 q4[8];
            #pragma unroll
            for (int i = 0; i < 8; i++)
                q4[i] = *(const float4*)&Qs[(ty * 8 + i) * 64 + k0];
            #pragma unroll
            for (int kq = 0; kq < 4; kq++) {
                float4 kv = *(const float4*)&KsT[(k0 + kq) * 64 + tx * 4];
                #pragma unroll
                for (int i = 0; i < 8; i++) {
                    float qv = (kq == 0) ? q4[i].x : (kq == 1) ? q4[i].y :
                               (kq == 2) ? q4[i].z : q4[i].w;
                    s[i][0] += qv * kv.x; s[i][1] += qv * kv.y;
                    s[i][2] += qv * kv.z; s[i][3] += qv * kv.w;
                }
            }
        }

        float p[8][4];
        #pragma unroll
        for (int i = 0; i < 8; i++) {
            float sc0 = s[i][0]*ATT_SCALE, sc1 = s[i][1]*ATT_SCALE;
            float sc2 = s[i][2]*ATT_SCALE, sc3 = s[i][3]*ATT_SCALE;
            float mloc = fmaxf(fmaxf(sc0, sc1), fmaxf(sc2, sc3));
            #pragma unroll
            for (int off = 8; off; off >>= 1)
                mloc = fmaxf(mloc, __shfl_xor_sync(0xffffffffu, mloc, off, 16));
            float mnew = fmaxf(mrow[i], mloc);
            float corr = expf(mrow[i] - mnew);
            p[i][0] = expf(sc0 - mnew); p[i][1] = expf(sc1 - mnew);
            p[i][2] = expf(sc2 - mnew); p[i][3] = expf(sc3 - mnew);
            float ps = p[i][0] + p[i][1] + p[i][2] + p[i][3];
            #pragma unroll
            for (int off = 8; off; off >>= 1)
                ps += __shfl_xor_sync(0xffffffffu, ps, off, 16);
            lrow[i] = lrow[i] * corr + ps;
            mrow[i] = mnew;
            acc[i][0] *= corr; acc[i][1] *= corr;
            acc[i][2] *= corr; acc[i][3] *= corr;
        }

        __syncthreads();
        #pragma unroll
        for (int i = 0; i < 8; i++) {
            float4 pv = make_float4(p[i][0], p[i][1], p[i][2], p[i][3]);
            *(float4*)&KsT[(ty * 8 + i) * 64 + tx * 4] = pv;
        }
        __syncthreads();

        for (int s0 = 0; s0 < 64; s0 += 4) {
            float4 p4[8];
            #pragma unroll
            for (int i = 0; i < 8; i++)
                p4[i] = *(const float4*)&KsT[(ty * 8 + i) * 64 + s0];
            #pragma unroll
            for (int sq = 0; sq < 4; sq++) {
                float4 vv = *(const float4*)&Vs[(s0 + sq) * 64 + tx * 4];
                #pragma unroll
                for (int i = 0; i < 8; i++) {
                    float pvv = (sq == 0) ? p4[i].x : (sq == 1) ? p4[i].y :
                                (sq == 2) ? p4[i].z : p4[i].w;
                    acc[i][0] += pvv * vv.x; acc[i][1] += pvv * vv.y;
                    acc[i][2] += pvv * vv.z; acc[i][3] += pvv * vv.w;
                }
            }
        }
    }

    #pragma unroll
    for (int i = 0; i < 8; i++) {
        float inv = 1.0f / lrow[i];
        int r = ty * 8 + i, d = tx * 4;
        float* dst = o + (size_t)(b * TOK + qt0 + r) * HID + hh * HD + d;
        dst[0] = acc[i][0] * inv; dst[1] = acc[i][1] * inv;
        dst[2] = acc[i][2] * inv; dst[3] = acc[i][3] * inv;
    }
}

// ================= misc small kernels =================
__global__ void tconv_kernel(const float* __restrict__ w, float* __restrict__ wT) {
    int idx = blockIdx.x * 256 + threadIdx.x;
    if (idx >= HID * KPATCH) return;
    int d = idx / KPATCH, k = idx % KPATCH;
    wT[k * HID + d] = w[idx];
}

__global__ void patch_kernel(const float* __restrict__ x, float* __restrict__ xp) {
    int idx = blockIdx.x * 256 + threadIdx.x;
    if (idx >= MROWS * KPATCH) return;
    int m = idx / KPATCH, k = idx % KPATCH;
    int b = m >> 10, tok = m & 1023, gy = tok >> 5, gx = tok & 31;
    int c = k >> 6, r = k & 63, p = r >> 3, q = r & 7;
    xp[idx] = x[((size_t)(b * CCH + c) * IMG + (gy * 8 + p)) * IMG + gx * 8 + q];
}

__global__ void te0_kernel(const int* __restrict__ t, float* __restrict__ te0) {
    int idx = blockIdx.x * 256 + threadIdx.x;
    if (idx >= BATCH * HID) return;
    int b = idx / HID, d = idx % HID;
    te0[idx] = posemb(t[b], d);
}

__global__ void unpatch_kernel(const float* __restrict__ y, float* __restrict__ out) {
    int idx = blockIdx.x * 256 + threadIdx.x;
    if (idx >= BATCH * CCH * IMG * IMG) return;
    int b = idx / (CCH * IMG * IMG);
    int rem = idx % (CCH * IMG * IMG);
    int c = rem / (IMG * IMG);
    int pix = rem % (IMG * IMG);
    int yy = pix >> 8, xx = pix & 255;
    int gy = yy >> 3, p = yy & 7, gx = xx >> 3, q = xx & 7;
    out[idx] = y[(size_t)(b * TOK + gy * 32 + gx) * KPATCH + p * 24 + q * 3 + c];
}

// ================= host launcher =================
static float* symAddr(const void* sym) {
    void* p = nullptr;
    cudaGetSymbolAddress(&p, sym);
    return (float*)p;
}

extern "C" void kernel_launch(void* const* d_in, const int* in_sizes, int n_in,
                              void* d_out, int out_size)
{
    const float* x       = (const float*)d_in[0];
    const int*   t       = (const int*)  d_in[1];
    const float* conv_w  = (const float*)d_in[2];
    const float* conv_b  = (const float*)d_in[3];
    const float* te_w1   = (const float*)d_in[4];
    const float* te_b1   = (const float*)d_in[5];
    const float* te_w2   = (const float*)d_in[6];
    const float* te_b2   = (const float*)d_in[7];
    const float* ln1_g   = (const float*)d_in[8];
    const float* ln1_b   = (const float*)d_in[9];
    const float* ln2_g   = (const float*)d_in[10];
    const float* ln2_b   = (const float*)d_in[11];
    const float* qkv_w   = (const float*)d_in[12];
    const float* qkv_b   = (const float*)d_in[13];
    const float* mha_w1  = (const float*)d_in[14];
    const float* mha_b1  = (const float*)d_in[15];
    const float* mha_w2  = (const float*)d_in[16];
    const float* mha_b2  = (const float*)d_in[17];
    const float* ss_w1   = (const float*)d_in[18];
    const float* ss_b1   = (const float*)d_in[19];
    const float* ss_w2   = (const float*)d_in[20];
    const float* ss_b2   = (const float*)d_in[21];
    const float* ffn_w1  = (const float*)d_in[22];
    const float* ffn_b1  = (const float*)d_in[23];
    const float* ffn_w2  = (const float*)d_in[24];
    const float* ffn_b2  = (const float*)d_in[25];
    const float* lnf_g   = (const float*)d_in[26];
    const float* lnf_b   = (const float*)d_in[27];
    const float* out_w   = (const float*)d_in[28];
    const float* out_b   = (const float*)d_in[29];
    float* out = (float*)d_out;

    float* xp    = symAddr(g_xp);
    float* cwT   = symAddr(g_cwT);
    float* h     = symAddr(g_h);
    float* z     = symAddr(g_z);
    float* qkv   = symAddr(g_qkv);
    float* attno = symAddr(g_attno);
    float* mid   = symAddr(g_mid);
    float* te0   = symAddr(g_te0);
    float* tmid  = symAddr(g_tmid);
    float* te    = symAddr(g_te);
    float* ssmid = symAddr(g_ssmid);
    float* ssb   = symAddr(g_ss);
    float* yb    = symAddr(g_y);

    // --- patchify + pos emb ---
    tconv_kernel<<<(HID * KPATCH + 255) / 256, 256>>>(conv_w, cwT);
    patch_kernel<<<(MROWS * KPATCH + 255) / 256, 256>>>(x, xp);
    gemm_tc<3><<<dim3(HID / BN, MROWS / BM), 256>>>(xp, cwT, conv_b, h,
                                                    MROWS, HID, KPATCH, nullptr);

    // --- timestep embedding MLP ---
    te0_kernel<<<(BATCH * HID + 255) / 256, 256>>>(t, te0);
    smallgemm_kernel<1><<<dim3(HID / 128, 1), 128>>>(te0, te_w1, te_b1, tmid,
                                                     HID, HID, 0, 0, 0, 0);
    smallgemm_kernel<0><<<dim3(HID / 128, 1), 128>>>(tmid, te_w2, te_b2, te,
                                                     HID, HID, 0, 0, 0, 0);

    // --- all 12 layers' adaLN modulation vectors up front ---
    smallgemm_kernel<1><<<dim3(SS6 / 128, NLAYER), 128>>>(
        te, ss_w1, ss_b1, ssmid, HID, SS6,
        0, (long)HID * SS6, SS6, (long)BATCH * SS6);
    smallgemm_kernel<0><<<dim3(SS6 / 128, NLAYER), 128>>>(
        ssmid, ss_w2, ss_b2, ssb, SS6, SS6,
        (long)BATCH * SS6, (long)SS6 * SS6, SS6, (long)BATCH * SS6);

    // --- transformer layers ---
    for (int l = 0; l < NLAYER; l++) {
        const float* ssl = ssb + (size_t)l * BATCH * SS6;

        ln_mod_kernel<<<MROWS, 256>>>(h, z, ln1_g + l * HID, ln1_b + l * HID,
                                      ssl, 0, HID);
        gemm_tc<0><<<dim3(H3 / BN, MROWS / BM), 256>>>(
            z, qkv_w + (size_t)l * HID * H3, qkv_b + l * H3, qkv,
            MROWS, H3, HID, nullptr);
        flash_kernel<<<dim3(TOK / 64, BATCH * NHEAD), 128>>>(qkv, attno);
        gemm_tc<1><<<dim3(H4 / BN, MROWS / BM), 256>>>(
            attno, mha_w1 + (size_t)l * HID * H4, mha_b1 + l * H4, mid,
            MROWS, H4, HID, nullptr);
        gemm_tc<2><<<dim3(HID / BN, MROWS / BM), 256>>>(
            mid, mha_w2 + (size_t)l * H4 * HID, mha_b2 + l * HID, h,
            MROWS, HID, H4, ssl + 2 * HID);

        ln_mod_kernel<<<MROWS, 256>>>(h, z, ln2_g + l * HID, ln2_b + l * HID,
                                      ssl, 3 * HID, 4 * HID);
        gemm_tc<1><<<dim3(H4 / BN, MROWS / BM), 256>>>(
            z, ffn_w1 + (size_t)l * HID * H4, ffn_b1 + l * H4, mid,
            MROWS, H4, HID, nullptr);
        gemm_tc<2><<<dim3(HID / BN, MROWS / BM), 256>>>(
            mid, ffn_w2 + (size_t)l * H4 * HID, ffn_b2 + l * HID, h,
            MROWS, HID, H4, ssl + 5 * HID);
    }

    // --- final LN, projection, unpatchify ---
    ln_mod_kernel<<<MROWS, 256>>>(h, z, lnf_g, lnf_b, nullptr, 0, 0);
    gemm_tc<0><<<dim3((KPATCH + BN - 1) / BN, MROWS / BM), 256>>>(
        z, out_w, out_b, yb, MROWS, KPATCH, HID, nullptr);
    unpatch_kernel<<<(BATCH * CCH * IMG * IMG + 255) / 256, 256>>>(yb, out);
}

// round 10
// speedup vs baseline: 2.4115x; 1.1739x over previous
#include <cuda_runtime.h>
#include <cuda_bf16.h>
#include <math.h>
#include <stdint.h>

// ---------------- problem constants ----------------
#define BATCH 8
#define CCH 3
#define IMG 256
#define PP 8
#define HID 768
#define NLAYER 12
#define NHEAD 12
#define HD 64
#define TOK 1024          // (256/8)^2
#define MROWS (BATCH*TOK) // 8192
#define KPATCH (CCH*PP*PP) // 192
#define SS6 (6*HID)       // 4608
#define H4 (4*HID)        // 3072
#define H3 (3*HID)        // 2304
#define ATT_SCALE 0.036084391824351615f  // 1/sqrt(768)

// ---------------- scratch (device globals; no allocation APIs) ----------------
__device__ float g_xp[MROWS*KPATCH];
__device__ float g_cwT[KPATCH*HID];
__device__ float g_h[MROWS*HID];
__device__ float g_z[MROWS*HID];
__device__ float g_qkv[MROWS*H3];
__device__ float g_attno[MROWS*HID];
__device__ float g_mid[MROWS*H4];
__device__ float g_te0[BATCH*HID];
__device__ float g_tmid[BATCH*HID];
__device__ float g_te[BATCH*HID];
__device__ float g_ssmid[NLAYER*BATCH*SS6];
__device__ float g_ss[NLAYER*BATCH*SS6];
__device__ float g_y[MROWS*KPATCH];

// ---------------- helpers ----------------
__device__ __forceinline__ float posemb(int pos, int d) {
    int j = d >> 1;
    float freq = expf(-9.210340371976184f * (float)(2 * j) * (1.0f / 768.0f));
    float th = (float)pos * freq;
    return (d & 1) ? cosf(th) : sinf(th);
}

__device__ __forceinline__ float to_tf32(float x) {
    float r;
    asm("cvt.rna.tf32.f32 %0, %1;" : "=f"(r) : "f"(x));
    return r;
}

__device__ __forceinline__ void mma_tf32(float c[4],
    uint32_t a0, uint32_t a1, uint32_t a2, uint32_t a3,
    uint32_t b0, uint32_t b1)
{
    asm volatile(
        "mma.sync.aligned.m16n8k8.row.col.f32.tf32.tf32.f32 "
        "{%0,%1,%2,%3}, {%4,%5,%6,%7}, {%8,%9}, {%0,%1,%2,%3};\n"
        : "+f"(c[0]), "+f"(c[1]), "+f"(c[2]), "+f"(c[3])
        : "r"(a0), "r"(a1), "r"(a2), "r"(a3), "r"(b0), "r"(b1));
}

// ================= main GEMM (tf32 tensor cores) ==========================
// C[M,N] = A[M,K] @ B[K,N] (+bias, epilogue), fp32 in/out, tf32 mma inside.
// EPI: 0 = bias; 1 = gelu(acc+bias); 2 = C += alpha[b,n]*(acc+bias);
//      3 = acc + bias + posemb(tok, n)
#define BM 128
#define BN 128
#define BK 16
#define SPAD 8
#define SLD (BM + SPAD)   // 136

template<int EPI>
__global__ void __launch_bounds__(256)
gemm_tc(const float* __restrict__ A, const float* __restrict__ B,
        const float* __restrict__ bias, float* __restrict__ C,
        int M, int N, int K, const float* __restrict__ alpha)
{
    __shared__ float As[2][BK][SLD];   // [k][m]
    __shared__ float Bs[2][BK][SLD];   // [k][n]

    int tid = threadIdx.x;
    int wid = tid >> 5, lane = tid & 31;
    int groupID = lane >> 2, tig = lane & 3;
    int warpM = (wid & 1) * 64;
    int warpN = (wid >> 1) * 32;
    int bm = blockIdx.y * BM, bn = blockIdx.x * BN;

    float acc[4][4][4];
    #pragma unroll
    for (int i = 0; i < 4; i++)
        #pragma unroll
        for (int j = 0; j < 4; j++)
            #pragma unroll
            for (int r = 0; r < 4; r++) acc[i][j][r] = 0.f;

    int aRow = tid >> 1;
    int aC = (tid & 1) * 8;
    int bRow = tid >> 4;
    int bC = (tid & 15) * 8;

    const float* aPtr = A + (size_t)(bm + aRow) * K + aC;
    const float* bPtr = B + (size_t)bRow * N + bn + bC;
    int bOk0 = (bn + bC) < N;
    int bOk1 = (bn + bC + 4) < N;

    float4 pa0, pa1, pb0, pb1;
    const float4 z4 = make_float4(0.f, 0.f, 0.f, 0.f);

    pa0 = *(const float4*)(aPtr);
    pa1 = *(const float4*)(aPtr + 4);
    pb0 = bOk0 ? *(const float4*)(bPtr) : z4;
    pb1 = bOk1 ? *(const float4*)(bPtr + 4) : z4;

    {
        As[0][aC + 0][aRow] = to_tf32(pa0.x); As[0][aC + 1][aRow] = to_tf32(pa0.y);
        As[0][aC + 2][aRow] = to_tf32(pa0.z); As[0][aC + 3][aRow] = to_tf32(pa0.w);
        As[0][aC + 4][aRow] = to_tf32(pa1.x); As[0][aC + 5][aRow] = to_tf32(pa1.y);
        As[0][aC + 6][aRow] = to_tf32(pa1.z); As[0][aC + 7][aRow] = to_tf32(pa1.w);
        float4 q0 = make_float4(to_tf32(pb0.x), to_tf32(pb0.y), to_tf32(pb0.z), to_tf32(pb0.w));
        float4 q1 = make_float4(to_tf32(pb1.x), to_tf32(pb1.y), to_tf32(pb1.z), to_tf32(pb1.w));
        *(float4*)&Bs[0][bRow][bC]     = q0;
        *(float4*)&Bs[0][bRow][bC + 4] = q1;
    }
    __syncthreads();

    int nTiles = K / BK;
    int cur = 0;
    for (int tI = 0; tI < nTiles; tI++) {
        int hasNext = (tI + 1) < nTiles;
        if (hasNext) {
            int koff = (tI + 1) * BK;
            pa0 = *(const float4*)(aPtr + koff);
            pa1 = *(const float4*)(aPtr + koff + 4);
            pb0 = bOk0 ? *(const float4*)(bPtr + (size_t)koff * N) : z4;
            pb1 = bOk1 ? *(const float4*)(bPtr + (size_t)koff * N + 4) : z4;
        }

        #pragma unroll
        for (int ks = 0; ks < 2; ks++) {
            int kb = ks * 8;
            uint32_t af[4][4];
            #pragma unroll
            for (int mi = 0; mi < 4; mi++) {
                int mr = warpM + mi * 16 + groupID;
                af[mi][0] = __float_as_uint(As[cur][kb + tig][mr]);
                af[mi][1] = __float_as_uint(As[cur][kb + tig][mr + 8]);
                af[mi][2] = __float_as_uint(As[cur][kb + tig + 4][mr]);
                af[mi][3] = __float_as_uint(As[cur][kb + tig + 4][mr + 8]);
            }
            uint32_t bf[4][2];
            #pragma unroll
            for (int ni = 0; ni < 4; ni++) {
                int nc = warpN + ni * 8 + groupID;
                bf[ni][0] = __float_as_uint(Bs[cur][kb + tig][nc]);
                bf[ni][1] = __float_as_uint(Bs[cur][kb + tig + 4][nc]);
            }
            #pragma unroll
            for (int mi = 0; mi < 4; mi++)
                #pragma unroll
                for (int ni = 0; ni < 4; ni++)
                    mma_tf32(acc[mi][ni], af[mi][0], af[mi][1], af[mi][2], af[mi][3],
                             bf[ni][0], bf[ni][1]);
        }

        if (hasNext) {
            int nxt = cur ^ 1;
            As[nxt][aC + 0][aRow] = to_tf32(pa0.x); As[nxt][aC + 1][aRow] = to_tf32(pa0.y);
            As[nxt][aC + 2][aRow] = to_tf32(pa0.z); As[nxt][aC + 3][aRow] = to_tf32(pa0.w);
            As[nxt][aC + 4][aRow] = to_tf32(pa1.x); As[nxt][aC + 5][aRow] = to_tf32(pa1.y);
            As[nxt][aC + 6][aRow] = to_tf32(pa1.z); As[nxt][aC + 7][aRow] = to_tf32(pa1.w);
            float4 q0 = make_float4(to_tf32(pb0.x), to_tf32(pb0.y), to_tf32(pb0.z), to_tf32(pb0.w));
            float4 q1 = make_float4(to_tf32(pb1.x), to_tf32(pb1.y), to_tf32(pb1.z), to_tf32(pb1.w));
            *(float4*)&Bs[nxt][bRow][bC]     = q0;
            *(float4*)&Bs[nxt][bRow][bC + 4] = q1;
            __syncthreads();
            cur = nxt;
        }
    }

    #pragma unroll
    for (int mi = 0; mi < 4; mi++) {
        #pragma unroll
        for (int ni = 0; ni < 4; ni++) {
            int row0 = bm + warpM + mi * 16 + groupID;
            int col = bn + warpN + ni * 8 + tig * 2;
            if (col >= N) continue;
            #pragma unroll
            for (int half = 0; half < 2; half++) {
                int mrow = row0 + half * 8;
                float v0 = acc[mi][ni][half * 2 + 0] + bias[col];
                float v1 = acc[mi][ni][half * 2 + 1] + bias[col + 1];
                size_t idx = (size_t)mrow * N + col;
                if (EPI == 1) {
                    v0 = 0.5f * v0 * (1.0f + erff(v0 * 0.70710678118654752f));
                    v1 = 0.5f * v1 * (1.0f + erff(v1 * 0.70710678118654752f));
                    C[idx] = v0; C[idx + 1] = v1;
                } else if (EPI == 2) {
                    int bb = mrow >> 10;
                    C[idx]     = C[idx]     + alpha[bb * SS6 + col]     * v0;
                    C[idx + 1] = C[idx + 1] + alpha[bb * SS6 + col + 1] * v1;
                } else if (EPI == 3) {
                    int tok = mrow & (TOK - 1);
                    C[idx]     = v0 + posemb(tok, col);
                    C[idx + 1] = v1 + posemb(tok, col + 1);
                } else {
                    C[idx] = v0; C[idx + 1] = v1;
                }
            }
        }
    }
}

// ============ small-M GEMM (M=8): out[8,N] = A[8,K] @ W[K,N] + b, opt silu ========
template<int SILU>
__global__ void __launch_bounds__(128)
smallgemm_kernel(const float* __restrict__ A, const float* __restrict__ W,
                 const float* __restrict__ bias, float* __restrict__ out,
                 int K, int N, long aStride, long wStride, long bStride, long oStride)
{
    int l = blockIdx.y;
    const float* Ap = A + (size_t)l * aStride;
    const float* Wp = W + (size_t)l * wStride;
    const float* bp = bias + (size_t)l * bStride;
    float* op = out + (size_t)l * oStride;
    int col = blockIdx.x * 128 + threadIdx.x;

    __shared__ float As[8][128];
    float acc[8];
    #pragma unroll
    for (int m = 0; m < 8; m++) acc[m] = 0.f;

    for (int k0 = 0; k0 < K; k0 += 128) {
        #pragma unroll
        for (int m = 0; m < 8; m++) As[m][threadIdx.x] = Ap[m * K + k0 + threadIdx.x];
        __syncthreads();
        #pragma unroll 4
        for (int kk = 0; kk < 128; kk++) {
            float w = Wp[(size_t)(k0 + kk) * N + col];
            #pragma unroll
            for (int m = 0; m < 8; m++) acc[m] += As[m][kk] * w;
        }
        __syncthreads();
    }
    #pragma unroll
    for (int m = 0; m < 8; m++) {
        float v = acc[m] + bp[col];
        if (SILU) v = v / (1.0f + expf(-v));
        op[(size_t)m * N + col] = v;
    }
}

// ================= LayerNorm + optional adaLN modulate =================
__global__ void __launch_bounds__(256)
ln_mod_kernel(const float* __restrict__ x, float* __restrict__ z,
              const float* __restrict__ g, const float* __restrict__ bta,
              const float* __restrict__ ss, int gOff, int bOff)
{
    int row = blockIdx.x;
    int tid = threadIdx.x;
    const float* xr = x + (size_t)row * HID;
    float v[3], s = 0.f, s2 = 0.f;
    #pragma unroll
    for (int k = 0; k < 3; k++) {
        v[k] = xr[tid + k * 256];
        s += v[k]; s2 += v[k] * v[k];
    }
    #pragma unroll
    for (int o = 16; o; o >>= 1) {
        s  += __shfl_xor_sync(0xffffffffu, s, o);
        s2 += __shfl_xor_sync(0xffffffffu, s2, o);
    }
    __shared__ float ws[8], ws2[8];
    if ((tid & 31) == 0) { ws[tid >> 5] = s; ws2[tid >> 5] = s2; }
    __syncthreads();
    if (tid < 32) {
        float a  = (tid < 8) ? ws[tid]  : 0.f;
        float a2 = (tid < 8) ? ws2[tid] : 0.f;
        #pragma unroll
        for (int o = 4; o; o >>= 1) {
            a  += __shfl_xor_sync(0xffffffffu, a, o);
            a2 += __shfl_xor_sync(0xffffffffu, a2, o);
        }
        if (tid == 0) { ws[0] = a; ws2[0] = a2; }
    }
    __syncthreads();
    float mean = ws[0] * (1.0f / HID);
    float var  = ws2[0] * (1.0f / HID) - mean * mean;
    float rs = rsqrtf(var + 1e-5f);
    int bb = row >> 10;
    #pragma unroll
    for (int k = 0; k < 3; k++) {
        int c = tid + k * 256;
        float y = (v[k] - mean) * rs * g[c] + bta[c];
        if (ss) y = ss[bb * SS6 + gOff + c] * y + ss[bb * SS6 + bOff + c];
        z[(size_t)row * HID + c] = y;
    }
}

// ================= flash attention (tf32 tensor cores) =====================
// One CTA: (batch b, head hh, 64 Q rows). 4 warps x 16 rows each.
// qkv layout: [b*1024+t, 2304]: q at h*64, k at 768+h*64, v at 1536+h*64.
// mma m16n8k8 row.col: A row-major, B col-major. K stored [s][d] serves
// directly as col-major B for S=Q@K^T; V stored [s][d] serves as col-major
// B for O=P@V. P round-trips through the Ks buffer.
// Smem strides: Ks 68 (s8=4: row-by-gid loads conflict-free),
//               Vs 72 (s8=8: row-by-tig loads conflict-free).
__global__ void __launch_bounds__(128)
flash_tc_kernel(const float* __restrict__ qkv, float* __restrict__ o)
{
    __shared__ float Ks[64][68];   // Q staging -> K tile -> P tile
    __shared__ float Vs[64][72];

    int bh = blockIdx.y;
    int b = bh / NHEAD, hh = bh % NHEAD;
    int qt0 = blockIdx.x * 64;
    int tid = threadIdx.x;
    int wid = tid >> 5, lane = tid & 31;
    int gid = lane >> 2, tig = lane & 3;
    int warpM = wid * 16;
    const float* base = qkv + (size_t)b * TOK * H3 + hh * HD;

    // ---- stage Q tile (64x64) into Ks, converted to tf32 ----
    {
        int r = tid >> 1, c0 = (tid & 1) * 32;
        const float* src = base + (size_t)(qt0 + r) * H3 + c0;
        #pragma unroll
        for (int i = 0; i < 8; i++) {
            float4 v = *(const float4*)(src + 4 * i);
            int c = c0 + 4 * i;
            Ks[r][c + 0] = to_tf32(v.x); Ks[r][c + 1] = to_tf32(v.y);
            Ks[r][c + 2] = to_tf32(v.z); Ks[r][c + 3] = to_tf32(v.w);
        }
    }
    __syncthreads();

    // ---- hoist Q fragments into registers (8 k-steps of m16k8) ----
    uint32_t qf[8][4];
    #pragma unroll
    for (int k = 0; k < 8; k++) {
        qf[k][0] = __float_as_uint(Ks[warpM + gid][k * 8 + tig]);
        qf[k][1] = __float_as_uint(Ks[warpM + gid + 8][k * 8 + tig]);
        qf[k][2] = __float_as_uint(Ks[warpM + gid][k * 8 + tig + 4]);
        qf[k][3] = __float_as_uint(Ks[warpM + gid + 8][k * 8 + tig + 4]);
    }

    float m0 = -1e30f, m1 = -1e30f, l0 = 0.f, l1 = 0.f;
    float oacc[8][4];
    #pragma unroll
    for (int nt = 0; nt < 8; nt++) {
        oacc[nt][0] = 0.f; oacc[nt][1] = 0.f;
        oacc[nt][2] = 0.f; oacc[nt][3] = 0.f;
    }

    for (int kt = 0; kt < TOK; kt += 64) {
        __syncthreads();   // Q frags / prev P+V consumption done
        {   // load K and V tiles (row-major [s][d], tf32-converted)
            int r = tid >> 1, c0 = (tid & 1) * 32;
            const float* ksrc = base + 768  + (size_t)(kt + r) * H3 + c0;
            const float* vsrc = base + 1536 + (size_t)(kt + r) * H3 + c0;
            #pragma unroll
            for (int i = 0; i < 8; i++) {
                float4 kv = *(const float4*)(ksrc + 4 * i);
                float4 vv = *(const float4*)(vsrc + 4 * i);
                int c = c0 + 4 * i;
                Ks[r][c + 0] = to_tf32(kv.x); Ks[r][c + 1] = to_tf32(kv.y);
                Ks[r][c + 2] = to_tf32(kv.z); Ks[r][c + 3] = to_tf32(kv.w);
                Vs[r][c + 0] = to_tf32(vv.x); Vs[r][c + 1] = to_tf32(vv.y);
                Vs[r][c + 2] = to_tf32(vv.z); Vs[r][c + 3] = to_tf32(vv.w);
            }
        }
        __syncthreads();

        // ---- S = Q @ K^T : 8 n-tiles x 8 k-steps ----
        float sf[8][4];
        #pragma unroll
        for (int nt = 0; nt < 8; nt++) {
            sf[nt][0] = 0.f; sf[nt][1] = 0.f; sf[nt][2] = 0.f; sf[nt][3] = 0.f;
        }
        #pragma unroll
        for (int k = 0; k < 8; k++) {
            #pragma unroll
            for (int nt = 0; nt < 8; nt++) {
                uint32_t b0 = __float_as_uint(Ks[nt * 8 + gid][k * 8 + tig]);
                uint32_t b1 = __float_as_uint(Ks[nt * 8 + gid][k * 8 + tig + 4]);
                mma_tf32(sf[nt], qf[k][0], qf[k][1], qf[k][2], qf[k][3], b0, b1);
            }
        }

        // ---- online softmax (rows gid and gid+8; 4 lanes/row via width-4 shfl) ----
        float tm0 = -1e30f, tm1 = -1e30f;
        #pragma unroll
        for (int nt = 0; nt < 8; nt++) {
            sf[nt][0] *= ATT_SCALE; sf[nt][1] *= ATT_SCALE;
            sf[nt][2] *= ATT_SCALE; sf[nt][3] *= ATT_SCALE;
            tm0 = fmaxf(tm0, fmaxf(sf[nt][0], sf[nt][1]));
            tm1 = fmaxf(tm1, fmaxf(sf[nt][2], sf[nt][3]));
        }
        tm0 = fmaxf(tm0, __shfl_xor_sync(0xffffffffu, tm0, 1, 4));
        tm0 = fmaxf(tm0, __shfl_xor_sync(0xffffffffu, tm0, 2, 4));
        tm1 = fmaxf(tm1, __shfl_xor_sync(0xffffffffu, tm1, 1, 4));
        tm1 = fmaxf(tm1, __shfl_xor_sync(0xffffffffu, tm1, 2, 4));
        float mn0 = fmaxf(m0, tm0), mn1 = fmaxf(m1, tm1);
        float cr0 = __expf(m0 - mn0), cr1 = __expf(m1 - mn1);
        float rs0 = 0.f, rs1 = 0.f;
        #pragma unroll
        for (int nt = 0; nt < 8; nt++) {   // sf becomes P in-place
            sf[nt][0] = __expf(sf[nt][0] - mn0);
            sf[nt][1] = __expf(sf[nt][1] - mn0);
            sf[nt][2] = __expf(sf[nt][2] - mn1);
            sf[nt][3] = __expf(sf[nt][3] - mn1);
            rs0 += sf[nt][0] + sf[nt][1];
            rs1 += sf[nt][2] + sf[nt][3];
        }
        rs0 += __shfl_xor_sync(0xffffffffu, rs0, 1, 4);
        rs0 += __shfl_xor_sync(0xffffffffu, rs0, 2, 4);
        rs1 += __shfl_xor_sync(0xffffffffu, rs1, 1, 4);
        rs1 += __shfl_xor_sync(0xffffffffu, rs1, 2, 4);
        l0 = l0 * cr0 + rs0;
        l1 = l1 * cr1 + rs1;
        m0 = mn0; m1 = mn1;
        #pragma unroll
        for (int nt = 0; nt < 8; nt++) {
            oacc[nt][0] *= cr0; oacc[nt][1] *= cr0;
            oacc[nt][2] *= cr1; oacc[nt][3] *= cr1;
        }

        // ---- write P into Ks (all warps' S reads of Ks are done) ----
        __syncthreads();
        #pragma unroll
        for (int nt = 0; nt < 8; nt++) {
            *(float2*)&Ks[warpM + gid][nt * 8 + tig * 2] =
                make_float2(to_tf32(sf[nt][0]), to_tf32(sf[nt][1]));
            *(float2*)&Ks[warpM + gid + 8][nt * 8 + tig * 2] =
                make_float2(to_tf32(sf[nt][2]), to_tf32(sf[nt][3]));
        }
        __syncthreads();

        // ---- O += P @ V : 8 k-steps (s) x 8 n-tiles (d) ----
        #pragma unroll
        for (int k = 0; k < 8; k++) {
            uint32_t a0 = __float_as_uint(Ks[warpM + gid][k * 8 + tig]);
            uint32_t a1 = __float_as_uint(Ks[warpM + gid + 8][k * 8 + tig]);
            uint32_t a2 = __float_as_uint(Ks[warpM + gid][k * 8 + tig + 4]);
            uint32_t a3 = __float_as_uint(Ks[warpM + gid + 8][k * 8 + tig + 4]);
            #pragma unroll
            for (int nt = 0; nt < 8; nt++) {
                uint32_t b0 = __float_as_uint(Vs[k * 8 + tig][nt * 8 + gid]);
                uint32_t b1 = __float_as_uint(Vs[k * 8 + tig + 4][nt * 8 + gid]);
                mma_tf32(oacc[nt], a0, a1, a2, a3, b0, b1);
            }
        }
    }

    // ---- normalize and write out ----
    float inv0 = 1.0f / l0, inv1 = 1.0f / l1;
    int row0 = b * TOK + qt0 + warpM + gid;
    #pragma unroll
    for (int nt = 0; nt < 8; nt++) {
        int col = hh * HD + nt * 8 + tig * 2;
        *(float2*)&o[(size_t)row0 * HID + col] =
            make_float2(oacc[nt][0] * inv0, oacc[nt][1] * inv0);
        *(float2*)&o[(size_t)(row0 + 8) * HID + col] =
            make_float2(oacc[nt][2] * inv1, oacc[nt][3] * inv1);
    }
}

// ================= misc small kernels =================
__global__ void tconv_kernel(const float* __restrict__ w, float* __restrict__ wT) {
    int idx = blockIdx.x * 256 + threadIdx.x;
    if (idx >= HID * KPATCH) return;
    int d = idx / KPATCH, k = idx % KPATCH;
    wT[k * HID + d] = w[idx];
}

__global__ void patch_kernel(const float* __restrict__ x, float* __restrict__ xp) {
    int idx = blockIdx.x * 256 + threadIdx.x;
    if (idx >= MROWS * KPATCH) return;
    int m = idx / KPATCH, k = idx % KPATCH;
    int b = m >> 10, tok = m & 1023, gy = tok >> 5, gx = tok & 31;
    int c = k >> 6, r = k & 63, p = r >> 3, q = r & 7;
    xp[idx] = x[((size_t)(b * CCH + c) * IMG + (gy * 8 + p)) * IMG + gx * 8 + q];
}

__global__ void te0_kernel(const int* __restrict__ t, float* __restrict__ te0) {
    int idx = blockIdx.x * 256 + threadIdx.x;
    if (idx >= BATCH * HID) return;
    int b = idx / HID, d = idx % HID;
    te0[idx] = posemb(t[b], d);
}

__global__ void unpatch_kernel(const float* __restrict__ y, float* __restrict__ out) {
    int idx = blockIdx.x * 256 + threadIdx.x;
    if (idx >= BATCH * CCH * IMG * IMG) return;
    int b = idx / (CCH * IMG * IMG);
    int rem = idx % (CCH * IMG * IMG);
    int c = rem / (IMG * IMG);
    int pix = rem % (IMG * IMG);
    int yy = pix >> 8, xx = pix & 255;
    int gy = yy >> 3, p = yy & 7, gx = xx >> 3, q = xx & 7;
    out[idx] = y[(size_t)(b * TOK + gy * 32 + gx) * KPATCH + p * 24 + q * 3 + c];
}

// ================= host launcher =================
static float* symAddr(const void* sym) {
    void* p = nullptr;
    cudaGetSymbolAddress(&p, sym);
    return (float*)p;
}

extern "C" void kernel_launch(void* const* d_in, const int* in_sizes, int n_in,
                              void* d_out, int out_size)
{
    const float* x       = (const float*)d_in[0];
    const int*   t       = (const int*)  d_in[1];
    const float* conv_w  = (const float*)d_in[2];
    const float* conv_b  = (const float*)d_in[3];
    const float* te_w1   = (const float*)d_in[4];
    const float* te_b1   = (const float*)d_in[5];
    const float* te_w2   = (const float*)d_in[6];
    const float* te_b2   = (const float*)d_in[7];
    const float* ln1_g   = (const float*)d_in[8];
    const float* ln1_b   = (const float*)d_in[9];
    const float* ln2_g   = (const float*)d_in[10];
    const float* ln2_b   = (const float*)d_in[11];
    const float* qkv_w   = (const float*)d_in[12];
    const float* qkv_b   = (const float*)d_in[13];
    const float* mha_w1  = (const float*)d_in[14];
    const float* mha_b1  = (const float*)d_in[15];
    const float* mha_w2  = (const float*)d_in[16];
    const float* mha_b2  = (const float*)d_in[17];
    const float* ss_w1   = (const float*)d_in[18];
    const float* ss_b1   = (const float*)d_in[19];
    const float* ss_w2   = (const float*)d_in[20];
    const float* ss_b2   = (const float*)d_in[21];
    const float* ffn_w1  = (const float*)d_in[22];
    const float* ffn_b1  = (const float*)d_in[23];
    const float* ffn_w2  = (const float*)d_in[24];
    const float* ffn_b2  = (const float*)d_in[25];
    const float* lnf_g   = (const float*)d_in[26];
    const float* lnf_b   = (const float*)d_in[27];
    const float* out_w   = (const float*)d_in[28];
    const float* out_b   = (const float*)d_in[29];
    float* out = (float*)d_out;

    float* xp    = symAddr(g_xp);
    float* cwT   = symAddr(g_cwT);
    float* h     = symAddr(g_h);
    float* z     = symAddr(g_z);
    float* qkv   = symAddr(g_qkv);
    float* attno = symAddr(g_attno);
    float* mid   = symAddr(g_mid);
    float* te0   = symAddr(g_te0);
    float* tmid  = symAddr(g_tmid);
    float* te    = symAddr(g_te);
    float* ssmid = symAddr(g_ssmid);
    float* ssb   = symAddr(g_ss);
    float* yb    = symAddr(g_y);

    // --- patchify + pos emb ---
    tconv_kernel<<<(HID * KPATCH + 255) / 256, 256>>>(conv_w, cwT);
    patch_kernel<<<(MROWS * KPATCH + 255) / 256, 256>>>(x, xp);
    gemm_tc<3><<<dim3(HID / BN, MROWS / BM), 256>>>(xp, cwT, conv_b, h,
                                                    MROWS, HID, KPATCH, nullptr);

    // --- timestep embedding MLP ---
    te0_kernel<<<(BATCH * HID + 255) / 256, 256>>>(t, te0);
    smallgemm_kernel<1><<<dim3(HID / 128, 1), 128>>>(te0, te_w1, te_b1, tmid,
                                                     HID, HID, 0, 0, 0, 0);
    smallgemm_kernel<0><<<dim3(HID / 128, 1), 128>>>(tmid, te_w2, te_b2, te,
                                                     HID, HID, 0, 0, 0, 0);

    // --- all 12 layers' adaLN modulation vectors up front ---
    smallgemm_kernel<1><<<dim3(SS6 / 128, NLAYER), 128>>>(
        te, ss_w1, ss_b1, ssmid, HID, SS6,
        0, (long)HID * SS6, SS6, (long)BATCH * SS6);
    smallgemm_kernel<0><<<dim3(SS6 / 128, NLAYER), 128>>>(
        ssmid, ss_w2, ss_b2, ssb, SS6, SS6,
        (long)BATCH * SS6, (long)SS6 * SS6, SS6, (long)BATCH * SS6);

    // --- transformer layers ---
    for (int l = 0; l < NLAYER; l++) {
        const float* ssl = ssb + (size_t)l * BATCH * SS6;

        ln_mod_kernel<<<MROWS, 256>>>(h, z, ln1_g + l * HID, ln1_b + l * HID,
                                      ssl, 0, HID);
        gemm_tc<0><<<dim3(H3 / BN, MROWS / BM), 256>>>(
            z, qkv_w + (size_t)l * HID * H3, qkv_b + l * H3, qkv,
            MROWS, H3, HID, nullptr);
        flash_tc_kernel<<<dim3(TOK / 64, BATCH * NHEAD), 128>>>(qkv, attno);
        gemm_tc<1><<<dim3(H4 / BN, MROWS / BM), 256>>>(
            attno, mha_w1 + (size_t)l * HID * H4, mha_b1 + l * H4, mid,
            MROWS, H4, HID, nullptr);
        gemm_tc<2><<<dim3(HID / BN, MROWS / BM), 256>>>(
            mid, mha_w2 + (size_t)l * H4 * HID, mha_b2 + l * HID, h,
            MROWS, HID, H4, ssl + 2 * HID);

        ln_mod_kernel<<<MROWS, 256>>>(h, z, ln2_g + l * HID, ln2_b + l * HID,
                                      ssl, 3 * HID, 4 * HID);
        gemm_tc<1><<<dim3(H4 / BN, MROWS / BM), 256>>>(
            z, ffn_w1 + (size_t)l * HID * H4, ffn_b1 + l * H4, mid,
            MROWS, H4, HID, nullptr);
        gemm_tc<2><<<dim3(HID / BN, MROWS / BM), 256>>>(
            mid, ffn_w2 + (size_t)l * H4 * HID, ffn_b2 + l * HID, h,
            MROWS, HID, H4, ssl + 5 * HID);
    }

    // --- final LN, projection, unpatchify ---
    ln_mod_kernel<<<MROWS, 256>>>(h, z, lnf_g, lnf_b, nullptr, 0, 0);
    gemm_tc<0><<<dim3((KPATCH + BN - 1) / BN, MROWS / BM), 256>>>(
        z, out_w, out_b, yb, MROWS, KPATCH, HID, nullptr);
    unpatch_kernel<<<(BATCH * CCH * IMG * IMG + 255) / 256, 256>>>(yb, out);
}

// round 13
// speedup vs baseline: 3.0108x; 1.2485x over previous
#include <cuda_runtime.h>
#include <cuda_bf16.h>
#include <math.h>
#include <stdint.h>

// ---------------- problem constants ----------------
#define BATCH 8
#define CCH 3
#define IMG 256
#define PP 8
#define HID 768
#define NLAYER 12
#define NHEAD 12
#define HD 64
#define TOK 1024          // (256/8)^2
#define MROWS (BATCH*TOK) // 8192
#define KPATCH (CCH*PP*PP) // 192
#define SS6 (6*HID)       // 4608
#define H4 (4*HID)        // 3072
#define H3 (3*HID)        // 2304
#define ATT_SCALE 0.036084391824351615f  // 1/sqrt(768)

// ---------------- scratch (device globals; no allocation APIs) ----------------
__device__ float g_xp[MROWS*KPATCH];
__device__ float g_cwT[KPATCH*HID];
__device__ float g_h[MROWS*HID];
__device__ float g_z[MROWS*HID];
__device__ float g_qkv[MROWS*H3];
__device__ float g_attno[MROWS*HID];
__device__ float g_mid[MROWS*H4];
__device__ float g_te0[BATCH*HID];
__device__ float g_tmid[BATCH*HID];
__device__ float g_te[BATCH*HID];
__device__ float g_ssmid[NLAYER*BATCH*SS6];
__device__ float g_ss[NLAYER*BATCH*SS6];
__device__ float g_y[MROWS*KPATCH];
// tf32-preconverted weight copies
__device__ float g_qkvw[NLAYER*HID*H3];
__device__ float g_mw1[NLAYER*HID*H4];
__device__ float g_mw2[NLAYER*H4*HID];
__device__ float g_fw1[NLAYER*HID*H4];
__device__ float g_fw2[NLAYER*H4*HID];
__device__ float g_outw[HID*KPATCH];

// ---------------- helpers ----------------
__device__ __forceinline__ float posemb(int pos, int d) {
    int j = d >> 1;
    float freq = expf(-9.210340371976184f * (float)(2 * j) * (1.0f / 768.0f));
    float th = (float)pos * freq;
    return (d & 1) ? cosf(th) : sinf(th);
}

__device__ __forceinline__ float to_tf32(float x) {
    float r;
    asm("cvt.rna.tf32.f32 %0, %1;" : "=f"(r) : "f"(x));
    return r;
}

__device__ __forceinline__ void mma_tf32(float c[4],
    uint32_t a0, uint32_t a1, uint32_t a2, uint32_t a3,
    uint32_t b0, uint32_t b1)
{
    asm volatile(
        "mma.sync.aligned.m16n8k8.row.col.f32.tf32.tf32.f32 "
        "{%0,%1,%2,%3}, {%4,%5,%6,%7}, {%8,%9}, {%0,%1,%2,%3};\n"
        : "+f"(c[0]), "+f"(c[1]), "+f"(c[2]), "+f"(c[3])
        : "r"(a0), "r"(a1), "r"(a2), "r"(a3), "r"(b0), "r"(b1));
}

__device__ __forceinline__ uint32_t smem_u32(const void* p) {
    return (uint32_t)__cvta_generic_to_shared(p);
}
__device__ __forceinline__ void cp_async16(uint32_t dst, const void* src, int srcBytes) {
    asm volatile("cp.async.cg.shared.global [%0], [%1], 16, %2;\n"
                 :: "r"(dst), "l"(src), "r"(srcBytes) : "memory");
}
__device__ __forceinline__ void cp_commit() {
    asm volatile("cp.async.commit_group;\n" ::: "memory");
}
__device__ __forceinline__ void cp_wait2() {
    asm volatile("cp.async.wait_group 2;\n" ::: "memory");
}

// ================= main GEMM (tf32 tensor cores, 4-stage cp.async) ===========
// C[M,N] = A[M,K] @ B[K,N] (+bias, epilogue). A and B are ALREADY tf32-rounded
// fp32 in gmem (producers/pre-conversion apply cvt.rna.tf32).
// EPI: 0 = bias (fp32 out); 1 = tf32(gelu(acc+bias)); 2 = C += alpha*(acc+bias);
//      3 = acc + bias + posemb(tok, n)
// Requires: M % 128 == 0, K % 16 == 0 and K >= 64, N % 4 == 0.
#define BM 128
#define BN 128
#define BK 16
#define A_ST 28                  // A smem row stride (floats)
#define B_ST 136                 // B smem row stride (floats)
#define A_SZ (BM * A_ST)         // 3584
#define B_SZ (BK * B_ST)         // 2176
#define STAGE_F (A_SZ + B_SZ)    // 5760 floats
#define NSTAGE 4
#define GEMM_SMEM_BYTES (STAGE_F * NSTAGE * 4)   // 92160

template<int EPI>
__global__ void __launch_bounds__(256, 2)
gemm_tc(const float* __restrict__ A, const float* __restrict__ B,
        const float* __restrict__ bias, float* __restrict__ C,
        int M, int N, int K, const float* __restrict__ alpha)
{
    extern __shared__ float sm[];
    int tid = threadIdx.x;
    int wid = tid >> 5, lane = tid & 31;
    int gid = lane >> 2, tig = lane & 3;
    int warpM = (wid & 1) * 64;
    int warpN = (wid >> 1) * 32;
    int bm = blockIdx.y * BM, bn = blockIdx.x * BN;

    float acc[4][4][4];
    #pragma unroll
    for (int i = 0; i < 4; i++)
        #pragma unroll
        for (int j = 0; j < 4; j++)
            #pragma unroll
            for (int r = 0; r < 4; r++) acc[i][j][r] = 0.f;

    // ---- async-copy mapping ----
    // A tile: 128 rows x 16 cols = 512 float4 chunks; thread does (m0,kc),(m0+64,kc)
    int m0 = tid >> 2, kc = tid & 3;
    // B tile: 16 rows x 128 cols = 512 float4 chunks; thread does (k0c,n4),(k0c+8,n4)
    int k0c = tid >> 5, n4 = tid & 31;
    int bOk = (bn + n4 * 4) < N;
    int bBytes = bOk ? 16 : 0;

    const float* aSrc0 = A + (size_t)(bm + m0) * K + kc * 4;
    const float* aSrc1 = A + (size_t)(bm + m0 + 64) * K + kc * 4;
    const float* bCol = B + (bOk ? (bn + n4 * 4) : 0);

    uint32_t smBase = smem_u32(sm);
    uint32_t aD0 = smBase + (m0 * A_ST + kc * 4) * 4;
    uint32_t aD1 = smBase + ((m0 + 64) * A_ST + kc * 4) * 4;
    uint32_t bD0 = smBase + (A_SZ + k0c * B_ST + n4 * 4) * 4;
    uint32_t bD1 = smBase + (A_SZ + (k0c + 8) * B_ST + n4 * 4) * 4;

    int nT = K / BK;

    // ---- prologue: issue stages 0..2 ----
    #pragma unroll
    for (int s = 0; s < NSTAGE - 1; s++) {
        uint32_t so = s * STAGE_F * 4;
        int kt = s * BK;
        cp_async16(aD0 + so, aSrc0 + kt, 16);
        cp_async16(aD1 + so, aSrc1 + kt, 16);
        cp_async16(bD0 + so, bCol + (size_t)(kt + k0c) * N, bBytes);
        cp_async16(bD1 + so, bCol + (size_t)(kt + k0c + 8) * N, bBytes);
        cp_commit();
    }

    for (int t = 0; t < nT; t++) {
        cp_wait2();
        __syncthreads();

        // issue stage t+3 (into buffer of tile t-1, all readers done)
        int tn = t + NSTAGE - 1;
        if (tn < nT) {
            uint32_t so = (tn & (NSTAGE - 1)) * STAGE_F * 4;
            int kt = tn * BK;
            cp_async16(aD0 + so, aSrc0 + kt, 16);
            cp_async16(aD1 + so, aSrc1 + kt, 16);
            cp_async16(bD0 + so, bCol + (size_t)(kt + k0c) * N, bBytes);
            cp_async16(bD1 + so, bCol + (size_t)(kt + k0c + 8) * N, bBytes);
        }
        cp_commit();

        const float* As_ = sm + (t & (NSTAGE - 1)) * STAGE_F;
        const float* Bs_ = As_ + A_SZ;

        #pragma unroll
        for (int ks = 0; ks < 2; ks++) {
            int kb = ks * 8;
            uint32_t af[4][4];
            #pragma unroll
            for (int mi = 0; mi < 4; mi++) {
                int mr = warpM + mi * 16 + gid;
                af[mi][0] = __float_as_uint(As_[mr * A_ST + kb + tig]);
                af[mi][1] = __float_as_uint(As_[(mr + 8) * A_ST + kb + tig]);
                af[mi][2] = __float_as_uint(As_[mr * A_ST + kb + tig + 4]);
                af[mi][3] = __float_as_uint(As_[(mr + 8) * A_ST + kb + tig + 4]);
            }
            uint32_t bf[4][2];
            #pragma unroll
            for (int ni = 0; ni < 4; ni++) {
                int nc = warpN + ni * 8 + gid;
                bf[ni][0] = __float_as_uint(Bs_[(kb + tig) * B_ST + nc]);
                bf[ni][1] = __float_as_uint(Bs_[(kb + tig + 4) * B_ST + nc]);
            }
            #pragma unroll
            for (int mi = 0; mi < 4; mi++)
                #pragma unroll
                for (int ni = 0; ni < 4; ni++)
                    mma_tf32(acc[mi][ni], af[mi][0], af[mi][1], af[mi][2], af[mi][3],
                             bf[ni][0], bf[ni][1]);
        }
    }

    // ---- epilogue ----
    #pragma unroll
    for (int mi = 0; mi < 4; mi++) {
        #pragma unroll
        for (int ni = 0; ni < 4; ni++) {
            int row0 = bm + warpM + mi * 16 + gid;
            int col = bn + warpN + ni * 8 + tig * 2;
            if (col >= N) continue;
            #pragma unroll
            for (int half = 0; half < 2; half++) {
                int mrow = row0 + half * 8;
                float v0 = acc[mi][ni][half * 2 + 0] + bias[col];
                float v1 = acc[mi][ni][half * 2 + 1] + bias[col + 1];
                size_t idx = (size_t)mrow * N + col;
                if (EPI == 1) {
                    v0 = 0.5f * v0 * (1.0f + erff(v0 * 0.70710678118654752f));
                    v1 = 0.5f * v1 * (1.0f + erff(v1 * 0.70710678118654752f));
                    C[idx] = to_tf32(v0); C[idx + 1] = to_tf32(v1);
                } else if (EPI == 2) {
                    int bb = mrow >> 10;
                    C[idx]     = C[idx]     + alpha[bb * SS6 + col]     * v0;
                    C[idx + 1] = C[idx + 1] + alpha[bb * SS6 + col + 1] * v1;
                } else if (EPI == 3) {
                    int tok = mrow & (TOK - 1);
                    C[idx]     = v0 + posemb(tok, col);
                    C[idx + 1] = v1 + posemb(tok, col + 1);
                } else {
                    C[idx] = v0; C[idx + 1] = v1;
                }
            }
        }
    }
}

// ============ tf32 pre-conversion (weights) ============
__global__ void cvt_kernel(const float4* __restrict__ src, float4* __restrict__ dst, int n4) {
    int i = blockIdx.x * 256 + threadIdx.x;
    if (i >= n4) return;
    float4 v = src[i];
    v.x = to_tf32(v.x); v.y = to_tf32(v.y);
    v.z = to_tf32(v.z); v.w = to_tf32(v.w);
    dst[i] = v;
}

// ============ small-M GEMM (M=8): out[8,N] = A[8,K] @ W[K,N] + b, opt silu ========
template<int SILU>
__global__ void __launch_bounds__(128)
smallgemm_kernel(const float* __restrict__ A, const float* __restrict__ W,
                 const float* __restrict__ bias, float* __restrict__ out,
                 int K, int N, long aStride, long wStride, long bStride, long oStride)
{
    int l = blockIdx.y;
    const float* Ap = A + (size_t)l * aStride;
    const float* Wp = W + (size_t)l * wStride;
    const float* bp = bias + (size_t)l * bStride;
    float* op = out + (size_t)l * oStride;
    int col = blockIdx.x * 128 + threadIdx.x;

    __shared__ float As[8][128];
    float acc[8];
    #pragma unroll
    for (int m = 0; m < 8; m++) acc[m] = 0.f;

    for (int k0 = 0; k0 < K; k0 += 128) {
        #pragma unroll
        for (int m = 0; m < 8; m++) As[m][threadIdx.x] = Ap[m * K + k0 + threadIdx.x];
        __syncthreads();
        #pragma unroll 4
        for (int kk = 0; kk < 128; kk++) {
            float w = Wp[(size_t)(k0 + kk) * N + col];
            #pragma unroll
            for (int m = 0; m < 8; m++) acc[m] += As[m][kk] * w;
        }
        __syncthreads();
    }
    #pragma unroll
    for (int m = 0; m < 8; m++) {
        float v = acc[m] + bp[col];
        if (SILU) v = v / (1.0f + expf(-v));
        op[(size_t)m * N + col] = v;
    }
}

// ================= LayerNorm + optional adaLN modulate (tf32 output) ============
__global__ void __launch_bounds__(256)
ln_mod_kernel(const float* __restrict__ x, float* __restrict__ z,
              const float* __restrict__ g, const float* __restrict__ bta,
              const float* __restrict__ ss, int gOff, int bOff)
{
    int row = blockIdx.x;
    int tid = threadIdx.x;
    const float* xr = x + (size_t)row * HID;
    float v[3], s = 0.f, s2 = 0.f;
    #pragma unroll
    for (int k = 0; k < 3; k++) {
        v[k] = xr[tid + k * 256];
        s += v[k]; s2 += v[k] * v[k];
    }
    #pragma unroll
    for (int o = 16; o; o >>= 1) {
        s  += __shfl_xor_sync(0xffffffffu, s, o);
        s2 += __shfl_xor_sync(0xffffffffu, s2, o);
    }
    __shared__ float ws[8], ws2[8];
    if ((tid & 31) == 0) { ws[tid >> 5] = s; ws2[tid >> 5] = s2; }
    __syncthreads();
    if (tid < 32) {
        float a  = (tid < 8) ? ws[tid]  : 0.f;
        float a2 = (tid < 8) ? ws2[tid] : 0.f;
        #pragma unroll
        for (int o = 4; o; o >>= 1) {
            a  += __shfl_xor_sync(0xffffffffu, a, o);
            a2 += __shfl_xor_sync(0xffffffffu, a2, o);
        }
        if (tid == 0) { ws[0] = a; ws2[0] = a2; }
    }
    __syncthreads();
    float mean = ws[0] * (1.0f / HID);
    float var  = ws2[0] * (1.0f / HID) - mean * mean;
    float rs = rsqrtf(var + 1e-5f);
    int bb = row >> 10;
    #pragma unroll
    for (int k = 0; k < 3; k++) {
        int c = tid + k * 256;
        float y = (v[k] - mean) * rs * g[c] + bta[c];
        if (ss) y = ss[bb * SS6 + gOff + c] * y + ss[bb * SS6 + bOff + c];
        z[(size_t)row * HID + c] = to_tf32(y);
    }
}

// ================= flash attention (tf32 tensor cores) =====================
__global__ void __launch_bounds__(128)
flash_tc_kernel(const float* __restrict__ qkv, float* __restrict__ o)
{
    __shared__ float Ks[64][68];   // Q staging -> K tile -> P tile
    __shared__ float Vs[64][72];

    int bh = blockIdx.y;
    int b = bh / NHEAD, hh = bh % NHEAD;
    int qt0 = blockIdx.x * 64;
    int tid = threadIdx.x;
    int wid = tid >> 5, lane = tid & 31;
    int gid = lane >> 2, tig = lane & 3;
    int warpM = wid * 16;
    const float* base = qkv + (size_t)b * TOK * H3 + hh * HD;

    {
        int r = tid >> 1, c0 = (tid & 1) * 32;
        const float* src = base + (size_t)(qt0 + r) * H3 + c0;
        #pragma unroll
        for (int i = 0; i < 8; i++) {
            float4 v = *(const float4*)(src + 4 * i);
            int c = c0 + 4 * i;
            Ks[r][c + 0] = to_tf32(v.x); Ks[r][c + 1] = to_tf32(v.y);
            Ks[r][c + 2] = to_tf32(v.z); Ks[r][c + 3] = to_tf32(v.w);
        }
    }
    __syncthreads();

    uint32_t qf[8][4];
    #pragma unroll
    for (int k = 0; k < 8; k++) {
        qf[k][0] = __float_as_uint(Ks[warpM + gid][k * 8 + tig]);
        qf[k][1] = __float_as_uint(Ks[warpM + gid + 8][k * 8 + tig]);
        qf[k][2] = __float_as_uint(Ks[warpM + gid][k * 8 + tig + 4]);
        qf[k][3] = __float_as_uint(Ks[warpM + gid + 8][k * 8 + tig + 4]);
    }

    float m0 = -1e30f, m1 = -1e30f, l0 = 0.f, l1 = 0.f;
    float oacc[8][4];
    #pragma unroll
    for (int nt = 0; nt < 8; nt++) {
        oacc[nt][0] = 0.f; oacc[nt][1] = 0.f;
        oacc[nt][2] = 0.f; oacc[nt][3] = 0.f;
    }

    for (int kt = 0; kt < TOK; kt += 64) {
        __syncthreads();
        {
            int r = tid >> 1, c0 = (tid & 1) * 32;
            const float* ksrc = base + 768  + (size_t)(kt + r) * H3 + c0;
            const float* vsrc = base + 1536 + (size_t)(kt + r) * H3 + c0;
            #pragma unroll
            for (int i = 0; i < 8; i++) {
                float4 kv = *(const float4*)(ksrc + 4 * i);
                float4 vv = *(const float4*)(vsrc + 4 * i);
                int c = c0 + 4 * i;
                Ks[r][c + 0] = to_tf32(kv.x); Ks[r][c + 1] = to_tf32(kv.y);
                Ks[r][c + 2] = to_tf32(kv.z); Ks[r][c + 3] = to_tf32(kv.w);
                Vs[r][c + 0] = to_tf32(vv.x); Vs[r][c + 1] = to_tf32(vv.y);
                Vs[r][c + 2] = to_tf32(vv.z); Vs[r][c + 3] = to_tf32(vv.w);
            }
        }
        __syncthreads();

        float sf[8][4];
        #pragma unroll
        for (int nt = 0; nt < 8; nt++) {
            sf[nt][0] = 0.f; sf[nt][1] = 0.f; sf[nt][2] = 0.f; sf[nt][3] = 0.f;
        }
        #pragma unroll
        for (int k = 0; k < 8; k++) {
            #pragma unroll
            for (int nt = 0; nt < 8; nt++) {
                uint32_t b0 = __float_as_uint(Ks[nt * 8 + gid][k * 8 + tig]);
                uint32_t b1 = __float_as_uint(Ks[nt * 8 + gid][k * 8 + tig + 4]);
                mma_tf32(sf[nt], qf[k][0], qf[k][1], qf[k][2], qf[k][3], b0, b1);
            }
        }

        float tm0 = -1e30f, tm1 = -1e30f;
        #pragma unroll
        for (int nt = 0; nt < 8; nt++) {
            sf[nt][0] *= ATT_SCALE; sf[nt][1] *= ATT_SCALE;
            sf[nt][2] *= ATT_SCALE; sf[nt][3] *= ATT_SCALE;
            tm0 = fmaxf(tm0, fmaxf(sf[nt][0], sf[nt][1]));
            tm1 = fmaxf(tm1, fmaxf(sf[nt][2], sf[nt][3]));
        }
        tm0 = fmaxf(tm0, __shfl_xor_sync(0xffffffffu, tm0, 1, 4));
        tm0 = fmaxf(tm0, __shfl_xor_sync(0xffffffffu, tm0, 2, 4));
        tm1 = fmaxf(tm1, __shfl_xor_sync(0xffffffffu, tm1, 1, 4));
        tm1 = fmaxf(tm1, __shfl_xor_sync(0xffffffffu, tm1, 2, 4));
        float mn0 = fmaxf(m0, tm0), mn1 = fmaxf(m1, tm1);
        float cr0 = __expf(m0 - mn0), cr1 = __expf(m1 - mn1);
        float rs0 = 0.f, rs1 = 0.f;
        #pragma unroll
        for (int nt = 0; nt < 8; nt++) {
            sf[nt][0] = __expf(sf[nt][0] - mn0);
            sf[nt][1] = __expf(sf[nt][1] - mn0);
            sf[nt][2] = __expf(sf[nt][2] - mn1);
            sf[nt][3] = __expf(sf[nt][3] - mn1);
            rs0 += sf[nt][0] + sf[nt][1];
            rs1 += sf[nt][2] + sf[nt][3];
        }
        rs0 += __shfl_xor_sync(0xffffffffu, rs0, 1, 4);
        rs0 += __shfl_xor_sync(0xffffffffu, rs0, 2, 4);
        rs1 += __shfl_xor_sync(0xffffffffu, rs1, 1, 4);
        rs1 += __shfl_xor_sync(0xffffffffu, rs1, 2, 4);
        l0 = l0 * cr0 + rs0;
        l1 = l1 * cr1 + rs1;
        m0 = mn0; m1 = mn1;
        #pragma unroll
        for (int nt = 0; nt < 8; nt++) {
            oacc[nt][0] *= cr0; oacc[nt][1] *= cr0;
            oacc[nt][2] *= cr1; oacc[nt][3] *= cr1;
        }

        __syncthreads();
        #pragma unroll
        for (int nt = 0; nt < 8; nt++) {
            *(float2*)&Ks[warpM + gid][nt * 8 + tig * 2] =
                make_float2(to_tf32(sf[nt][0]), to_tf32(sf[nt][1]));
            *(float2*)&Ks[warpM + gid + 8][nt * 8 + tig * 2] =
                make_float2(to_tf32(sf[nt][2]), to_tf32(sf[nt][3]));
        }
        __syncthreads();

        #pragma unroll
        for (int k = 0; k < 8; k++) {
            uint32_t a0 = __float_as_uint(Ks[warpM + gid][k * 8 + tig]);
            uint32_t a1 = __float_as_uint(Ks[warpM + gid + 8][k * 8 + tig]);
            uint32_t a2 = __float_as_uint(Ks[warpM + gid][k * 8 + tig + 4]);
            uint32_t a3 = __float_as_uint(Ks[warpM + gid + 8][k * 8 + tig + 4]);
            #pragma unroll
            for (int nt = 0; nt < 8; nt++) {
                uint32_t b0 = __float_as_uint(Vs[k * 8 + tig][nt * 8 + gid]);
                uint32_t b1 = __float_as_uint(Vs[k * 8 + tig + 4][nt * 8 + gid]);
                mma_tf32(oacc[nt], a0, a1, a2, a3, b0, b1);
            }
        }
    }

    // attno feeds gemm as A -> tf32-rounded output
    float inv0 = 1.0f / l0, inv1 = 1.0f / l1;
    int row0 = b * TOK + qt0 + warpM + gid;
    #pragma unroll
    for (int nt = 0; nt < 8; nt++) {
        int col = hh * HD + nt * 8 + tig * 2;
        *(float2*)&o[(size_t)row0 * HID + col] =
            make_float2(to_tf32(oacc[nt][0] * inv0), to_tf32(oacc[nt][1] * inv0));
        *(float2*)&o[(size_t)(row0 + 8) * HID + col] =
            make_float2(to_tf32(oacc[nt][2] * inv1), to_tf32(oacc[nt][3] * inv1));
    }
}

// ================= misc small kernels =================
__global__ void tconv_kernel(const float* __restrict__ w, float* __restrict__ wT) {
    int idx = blockIdx.x * 256 + threadIdx.x;
    if (idx >= HID * KPATCH) return;
    int d = idx / KPATCH, k = idx % KPATCH;
    wT[k * HID + d] = to_tf32(w[idx]);
}

__global__ void patch_kernel(const float* __restrict__ x, float* __restrict__ xp) {
    int idx = blockIdx.x * 256 + threadIdx.x;
    if (idx >= MROWS * KPATCH) return;
    int m = idx / KPATCH, k = idx % KPATCH;
    int b = m >> 10, tok = m & 1023, gy = tok >> 5, gx = tok & 31;
    int c = k >> 6, r = k & 63, p = r >> 3, q = r & 7;
    xp[idx] = to_tf32(x[((size_t)(b * CCH + c) * IMG + (gy * 8 + p)) * IMG + gx * 8 + q]);
}

__global__ void te0_kernel(const int* __restrict__ t, float* __restrict__ te0) {
    int idx = blockIdx.x * 256 + threadIdx.x;
    if (idx >= BATCH * HID) return;
    int b = idx / HID, d = idx % HID;
    te0[idx] = posemb(t[b], d);
}

__global__ void unpatch_kernel(const float* __restrict__ y, float* __restrict__ out) {
    int idx = blockIdx.x * 256 + threadIdx.x;
    if (idx >= BATCH * CCH * IMG * IMG) return;
    int b = idx / (CCH * IMG * IMG);
    int rem = idx % (CCH * IMG * IMG);
    int c = rem / (IMG * IMG);
    int pix = rem % (IMG * IMG);
    int yy = pix >> 8, xx = pix & 255;
    int gy = yy >> 3, p = yy & 7, gx = xx >> 3, q = xx & 7;
    out[idx] = y[(size_t)(b * TOK + gy * 32 + gx) * KPATCH + p * 24 + q * 3 + c];
}

// ================= host launcher =================
static float* symAddr(const void* sym) {
    void* p = nullptr;
    cudaGetSymbolAddress(&p, sym);
    return (float*)p;
}

extern "C" void kernel_launch(void* const* d_in, const int* in_sizes, int n_in,
                              void* d_out, int out_size)
{
    const float* x       = (const float*)d_in[0];
    const int*   t       = (const int*)  d_in[1];
    const float* conv_w  = (const float*)d_in[2];
    const float* conv_b  = (const float*)d_in[3];
    const float* te_w1   = (const float*)d_in[4];
    const float* te_b1   = (const float*)d_in[5];
    const float* te_w2   = (const float*)d_in[6];
    const float* te_b2   = (const float*)d_in[7];
    const float* ln1_g   = (const float*)d_in[8];
    const float* ln1_b   = (const float*)d_in[9];
    const float* ln2_g   = (const float*)d_in[10];
    const float* ln2_b   = (const float*)d_in[11];
    const float* qkv_w   = (const float*)d_in[12];
    const float* qkv_b   = (const float*)d_in[13];
    const float* mha_w1  = (const float*)d_in[14];
    const float* mha_b1  = (const float*)d_in[15];
    const float* mha_w2  = (const float*)d_in[16];
    const float* mha_b2  = (const float*)d_in[17];
    const float* ss_w1   = (const float*)d_in[18];
    const float* ss_b1   = (const float*)d_in[19];
    const float* ss_w2   = (const float*)d_in[20];
    const float* ss_b2   = (const float*)d_in[21];
    const float* ffn_w1  = (const float*)d_in[22];
    const float* ffn_b1  = (const float*)d_in[23];
    const float* ffn_w2  = (const float*)d_in[24];
    const float* ffn_b2  = (const float*)d_in[25];
    const float* lnf_g   = (const float*)d_in[26];
    const float* lnf_b   = (const float*)d_in[27];
    const float* out_w   = (const float*)d_in[28];
    const float* out_b   = (const float*)d_in[29];
    float* out = (float*)d_out;

    float* xp    = symAddr(g_xp);
    float* cwT   = symAddr(g_cwT);
    float* h     = symAddr(g_h);
    float* z     = symAddr(g_z);
    float* qkv   = symAddr(g_qkv);
    float* attno = symAddr(g_attno);
    float* mid   = symAddr(g_mid);
    float* te0   = symAddr(g_te0);
    float* tmid  = symAddr(g_tmid);
    float* te    = symAddr(g_te);
    float* ssmid = symAddr(g_ssmid);
    float* ssb   = symAddr(g_ss);
    float* yb    = symAddr(g_y);
    float* qkvw  = symAddr(g_qkvw);
    float* mw1   = symAddr(g_mw1);
    float* mw2   = symAddr(g_mw2);
    float* fw1   = symAddr(g_fw1);
    float* fw2   = symAddr(g_fw2);
    float* outw  = symAddr(g_outw);

    // opt-in to 92KB dynamic smem (idempotent; executed before capture too)
    cudaFuncSetAttribute(gemm_tc<0>, cudaFuncAttributeMaxDynamicSharedMemorySize, GEMM_SMEM_BYTES);
    cudaFuncSetAttribute(gemm_tc<1>, cudaFuncAttributeMaxDynamicSharedMemorySize, GEMM_SMEM_BYTES);
    cudaFuncSetAttribute(gemm_tc<2>, cudaFuncAttributeMaxDynamicSharedMemorySize, GEMM_SMEM_BYTES);
    cudaFuncSetAttribute(gemm_tc<3>, cudaFuncAttributeMaxDynamicSharedMemorySize, GEMM_SMEM_BYTES);

    // --- pre-convert weights to tf32 ---
    {
        int n;
        n = NLAYER * HID * H3 / 4;
        cvt_kernel<<<(n + 255) / 256, 256>>>((const float4*)qkv_w, (float4*)qkvw, n);
        n = NLAYER * HID * H4 / 4;
        cvt_kernel<<<(n + 255) / 256, 256>>>((const float4*)mha_w1, (float4*)mw1, n);
        cvt_kernel<<<(n + 255) / 256, 256>>>((const float4*)mha_w2, (float4*)mw2, n);
        cvt_kernel<<<(n + 255) / 256, 256>>>((const float4*)ffn_w1, (float4*)fw1, n);
        cvt_kernel<<<(n + 255) / 256, 256>>>((const float4*)ffn_w2, (float4*)fw2, n);
        n = HID * KPATCH / 4;
        cvt_kernel<<<(n + 255) / 256, 256>>>((const float4*)out_w, (float4*)outw, n);
    }

    // --- patchify + pos emb ---
    tconv_kernel<<<(HID * KPATCH + 255) / 256, 256>>>(conv_w, cwT);
    patch_kernel<<<(MROWS * KPATCH + 255) / 256, 256>>>(x, xp);
    gemm_tc<3><<<dim3(HID / BN, MROWS / BM), 256, GEMM_SMEM_BYTES>>>(
        xp, cwT, conv_b, h, MROWS, HID, KPATCH, nullptr);

    // --- timestep embedding MLP ---
    te0_kernel<<<(BATCH * HID + 255) / 256, 256>>>(t, te0);
    smallgemm_kernel<1><<<dim3(HID / 128, 1), 128>>>(te0, te_w1, te_b1, tmid,
                                                     HID, HID, 0, 0, 0, 0);
    smallgemm_kernel<0><<<dim3(HID / 128, 1), 128>>>(tmid, te_w2, te_b2, te,
                                                     HID, HID, 0, 0, 0, 0);

    // --- all 12 layers' adaLN modulation vectors up front ---
    smallgemm_kernel<1><<<dim3(SS6 / 128, NLAYER), 128>>>(
        te, ss_w1, ss_b1, ssmid, HID, SS6,
        0, (long)HID * SS6, SS6, (long)BATCH * SS6);
    smallgemm_kernel<0><<<dim3(SS6 / 128, NLAYER), 128>>>(
        ssmid, ss_w2, ss_b2, ssb, SS6, SS6,
        (long)BATCH * SS6, (long)SS6 * SS6, SS6, (long)BATCH * SS6);

    // --- transformer layers ---
    for (int l = 0; l < NLAYER; l++) {
        const float* ssl = ssb + (size_t)l * BATCH * SS6;

        ln_mod_kernel<<<MROWS, 256>>>(h, z, ln1_g + l * HID, ln1_b + l * HID,
                                      ssl, 0, HID);
        gemm_tc<0><<<dim3(H3 / BN, MROWS / BM), 256, GEMM_SMEM_BYTES>>>(
            z, qkvw + (size_t)l * HID * H3, qkv_b + l * H3, qkv,
            MROWS, H3, HID, nullptr);
        flash_tc_kernel<<<dim3(TOK / 64, BATCH * NHEAD), 128>>>(qkv, attno);
        gemm_tc<1><<<dim3(H4 / BN, MROWS / BM), 256, GEMM_SMEM_BYTES>>>(
            attno, mw1 + (size_t)l * HID * H4, mha_b1 + l * H4, mid,
            MROWS, H4, HID, nullptr);
        gemm_tc<2><<<dim3(HID / BN, MROWS / BM), 256, GEMM_SMEM_BYTES>>>(
            mid, mw2 + (size_t)l * H4 * HID, mha_b2 + l * HID, h,
            MROWS, HID, H4, ssl + 2 * HID);

        ln_mod_kernel<<<MROWS, 256>>>(h, z, ln2_g + l * HID, ln2_b + l * HID,
                                      ssl, 3 * HID, 4 * HID);
        gemm_tc<1><<<dim3(H4 / BN, MROWS / BM), 256, GEMM_SMEM_BYTES>>>(
            z, fw1 + (size_t)l * HID * H4, ffn_b1 + l * H4, mid,
            MROWS, H4, HID, nullptr);
        gemm_tc<2><<<dim3(HID / BN, MROWS / BM), 256, GEMM_SMEM_BYTES>>>(
            mid, fw2 + (size_t)l * H4 * HID, ffn_b2 + l * HID, h,
            MROWS, HID, H4, ssl + 5 * HID);
    }

    // --- final LN, projection, unpatchify ---
    ln_mod_kernel<<<MROWS, 256>>>(h, z, lnf_g, lnf_b, nullptr, 0, 0);
    gemm_tc<0><<<dim3((KPATCH + BN - 1) / BN, MROWS / BM), 256, GEMM_SMEM_BYTES>>>(
        z, outw, out_b, yb, MROWS, KPATCH, HID, nullptr);
    unpatch_kernel<<<(BATCH * CCH * IMG * IMG + 255) / 256, 256>>>(yb, out);
}